// round 13
// baseline (speedup 1.0000x reference)
#include <cuda_runtime.h>
#include <cuda_fp16.h>
#include <cstdint>

#define B_SZ   4
#define S_LEN  2048
#define NH     16
#define HD     64
#define MODEL  1024
#define KDIM   1024
#define M_ROWS 8192
#define PK     2048      // packed halves per row (hi16|lo16 interleave per 16 elems)
#define NQB    16
#define NKT    32

// ---- packed fp16 scratch layout (halves) ----
#define HP_AQ  0ull
#define HP_AK  (1ull * M_ROWS * PK)
#define HP_AV  (2ull * M_ROWS * PK)
#define HP_AOP (3ull * M_ROWS * PK)
#define HP_WSZ ((unsigned long long)MODEL * PK)
#define HP_W0  (4ull * M_ROWS * PK)
#define BH_SZ  (64ull * S_LEN * 128)
#define HP_QH  (HP_W0 + 4ull * HP_WSZ)
#define HP_KH  (HP_QH + BH_SZ)
#define HP_VH  (HP_KH + BH_SZ)
__device__ __half g_h16[HP_VH + BH_SZ];

// ============================ helpers ======================================
__device__ __forceinline__ uint32_t smem_u32(const void* p) {
    uint32_t a;
    asm("{ .reg .u64 t; cvta.to.shared.u64 t, %1; cvt.u32.u64 %0, t; }"
        : "=r"(a) : "l"(p));
    return a;
}

// split pair of floats into packed hi half2 + lo half2
__device__ __forceinline__ void split2(float x, float y, uint32_t& hi, uint32_t& lo) {
    __half2 h = __floats2half2_rn(x, y);
    float2 f = __half22float2(h);
    __half2 l = __floats2half2_rn(x - f.x, y - f.y);
    hi = *reinterpret_cast<uint32_t*>(&h);
    lo = *reinterpret_cast<uint32_t*>(&l);
}

#define CP_ASYNC16(dst, src) \
    asm volatile("cp.async.cg.shared.global [%0], [%1], 16;" :: "r"(dst), "l"(src))
#define CP_COMMIT() asm volatile("cp.async.commit_group;")
#define CP_WAIT1()  asm volatile("cp.async.wait_group 1;")
#define CP_WAIT0()  asm volatile("cp.async.wait_group 0;")

#define LDM_X4(r0, r1, r2, r3, addr) \
    asm volatile("ldmatrix.sync.aligned.m8n8.x4.shared.b16 {%0,%1,%2,%3}, [%4];" \
                 : "=r"(r0), "=r"(r1), "=r"(r2), "=r"(r3) : "r"(addr))

#define MMA16816(c, a, b0, b1) \
    asm volatile("mma.sync.aligned.m16n8k16.row.col.f32.f16.f16.f32 " \
                 "{%0,%1,%2,%3}, {%4,%5,%6,%7}, {%8,%9}, {%0,%1,%2,%3};" \
                 : "+f"((c)[0]), "+f"((c)[1]), "+f"((c)[2]), "+f"((c)[3]) \
                 : "r"((a)[0]), "r"((a)[1]), "r"((a)[2]), "r"((a)[3]), \
                   "r"(b0), "r"(b1))

// ============================ split-convert prepass ========================
struct CvtPair { const float* s; __half* d; };

__global__ __launch_bounds__(256) void cvt_multi_kernel(
    CvtPair p0, CvtPair p1, CvtPair p2, CvtPair p3, int n4)
{
    CvtPair p = (blockIdx.y == 0) ? p0 : (blockIdx.y == 1) ? p1
              : (blockIdx.y == 2) ? p2 : p3;
    int i = blockIdx.x * blockDim.x + threadIdx.x;
    if (i >= n4) return;
    float4 v = reinterpret_cast<const float4*>(p.s)[i];
    int row  = i >> 8;
    int kpos = (i & 255) << 2;
    size_t base = (size_t)row * PK + (size_t)(kpos >> 4) * 32 + (kpos & 15);
    uint32_t h0, l0, h1, l1;
    split2(v.x, v.y, h0, l0);
    split2(v.z, v.w, h1, l1);
    *reinterpret_cast<uint2*>(p.d + base)      = make_uint2(h0, h1);
    *reinterpret_cast<uint2*>(p.d + base + 16) = make_uint2(l0, l1);
}

// ============================ fp16-split HMMA GEMM =========================
// C = A @ W^T + bias.  CTA tile 128x128, 8 warps (64x32 warp tile), K staged
// 32, 2-stage cp.async pipeline.  2-PASS: (Ah+Al) x Wh.
// __launch_bounds__(256, 2) + single A-register-array pass sequencing (R13)
// so peak live regs ~113 < 128 -> 2 CTAs/SM with zero spills.
// gridDim.z selects one of up to 3 jobs (merged launches).
// mode 0: packed QK attn layout [bh][s][hi64|lo64] (scaled by oscale)
// mode 1: fp32 row-major [M,1024]
// mode 2: packed V transposed [bh][hi-d 0..63, lo-d 64..127][s]
struct GJob {
    const __half* A;
    const __half* W;
    const float*  bias;
    void*         C;
    int           mode;
    float         oscale;
};

#define GR 144
#define STAGE_BYTES (2 * 128 * GR)  // A tile + B tile = 36864
#define GEMM_SMEM (2 * STAGE_BYTES) // 73728

__global__ __launch_bounds__(256, 2) void hgemm_split_kernel(GJob j0, GJob j1, GJob j2)
{
    const GJob J = (blockIdx.z == 0) ? j0 : (blockIdx.z == 1) ? j1 : j2;
    const __half* Ap = J.A;
    const __half* Wp = J.W;
    const float* bias = J.bias;
    void* Cv = J.C;
    const int mode = J.mode;
    const float oscale = J.oscale;

    extern __shared__ char smem[];
    const uint32_t sb = smem_u32(smem);
    const int tid  = threadIdx.x;
    const int lane = tid & 31;
    const int wid  = tid >> 5;
    const int wm   = wid & 1;        // 2 warp-rows x 64
    const int wn   = wid >> 1;       // 4 warp-cols x 32

    const int row0 = blockIdx.y * 128;
    const int col0 = blockIdx.x * 128;

    const int lrow = tid >> 1;
    const int lhalf = (tid & 1) * 4;
    const __half* Ag = Ap + (size_t)(row0 + lrow) * PK + lhalf * 8;
    const __half* Wg = Wp + (size_t)(col0 + lrow) * PK + lhalf * 8;
    const uint32_t sA = sb + lrow * GR + lhalf * 16;
    const uint32_t sB = sA + 128 * GR;

    float c[4][4][4];
    #pragma unroll
    for (int mt = 0; mt < 4; mt++)
        #pragma unroll
        for (int nt = 0; nt < 4; nt++)
            #pragma unroll
            for (int q = 0; q < 4; q++)
                c[mt][nt][q] = 0.0f;

    const int arow = wm * 64 + (lane & 7) + ((lane >> 3) & 1) * 8;
    const uint32_t aoff = ((lane >> 4) & 1) * 16;
    const int brow = wn * 32 + (lane & 7) + ((lane >> 4) & 1) * 8;
    const uint32_t boff = ((lane >> 3) & 1) * 16;

    #pragma unroll
    for (int i = 0; i < 4; i++) {
        CP_ASYNC16(sA + i * 16, Ag + i * 8);
        CP_ASYNC16(sB + i * 16, Wg + i * 8);
    }
    CP_COMMIT();

    const int NSTAGE = KDIM / 32;
    for (int s = 0; s < NSTAGE; s++) {
        const int sel = s & 1;
        if (s + 1 < NSTAGE) {
            const int nsel = (s + 1) & 1;
            const __half* Agn = Ag + (size_t)(s + 1) * 64;
            const __half* Wgn = Wg + (size_t)(s + 1) * 64;
            #pragma unroll
            for (int i = 0; i < 4; i++) {
                CP_ASYNC16(sA + nsel * STAGE_BYTES + i * 16, Agn + i * 8);
                CP_ASYNC16(sB + nsel * STAGE_BYTES + i * 16, Wgn + i * 8);
            }
            CP_COMMIT();
            CP_WAIT1();
        } else {
            CP_WAIT0();
        }
        __syncthreads();

        const uint32_t Abase = sb + sel * STAGE_BYTES;
        const uint32_t Bbase = Abase + 128 * GR;

        #pragma unroll
        for (int kk = 0; kk < 2; kk++) {
            uint32_t a[4][4], bH[8];
            const uint32_t gH = kk * 2, gL = kk * 2 + 1;
            // B fragments for this k16 (reused by both passes)
            #pragma unroll
            for (int nt2 = 0; nt2 < 2; nt2++) {
                uint32_t bd = Bbase + (brow + nt2 * 16) * GR + boff;
                LDM_X4(bH[nt2*4+0], bH[nt2*4+1], bH[nt2*4+2], bH[nt2*4+3], bd + gH * 32);
            }
            // pass 1: A-hi
            #pragma unroll
            for (int mt = 0; mt < 4; mt++) {
                uint32_t ad = Abase + (arow + mt * 16) * GR + aoff;
                LDM_X4(a[mt][0], a[mt][1], a[mt][2], a[mt][3], ad + gH * 32);
            }
            #pragma unroll
            for (int mt = 0; mt < 4; mt++)
                #pragma unroll
                for (int nt = 0; nt < 4; nt++)
                    MMA16816(c[mt][nt], a[mt], bH[nt*2], bH[nt*2+1]);
            // pass 2: A-lo (reuse the same registers)
            #pragma unroll
            for (int mt = 0; mt < 4; mt++) {
                uint32_t ad = Abase + (arow + mt * 16) * GR + aoff;
                LDM_X4(a[mt][0], a[mt][1], a[mt][2], a[mt][3], ad + gL * 32);
            }
            #pragma unroll
            for (int mt = 0; mt < 4; mt++)
                #pragma unroll
                for (int nt = 0; nt < 4; nt++)
                    MMA16816(c[mt][nt], a[mt], bH[nt*2], bH[nt*2+1]);
        }
        __syncthreads();
    }

    const int mrow0 = row0 + wm * 64;
    const int ncol0 = col0 + wn * 32;
    #pragma unroll
    for (int mt = 0; mt < 4; mt++) {
        #pragma unroll
        for (int nt = 0; nt < 4; nt++) {
            const int n = ncol0 + nt * 8 + (lane & 3) * 2;
            const float2 bv = *reinterpret_cast<const float2*>(bias + n);
            const int m1 = mrow0 + mt * 16 + (lane >> 2);
            const int m2 = m1 + 8;
            float2 v1 = make_float2((c[mt][nt][0] + bv.x) * oscale,
                                    (c[mt][nt][1] + bv.y) * oscale);
            float2 v2 = make_float2((c[mt][nt][2] + bv.x) * oscale,
                                    (c[mt][nt][3] + bv.y) * oscale);
            if (mode == 1) {
                float* C = (float*)Cv;
                *reinterpret_cast<float2*>(C + (size_t)m1 * MODEL + n) = v1;
                *reinterpret_cast<float2*>(C + (size_t)m2 * MODEL + n) = v2;
            } else {
                __half* H = (__half*)Cv;
                const int hh = n >> 6, d = n & (HD - 1);
                #pragma unroll
                for (int t = 0; t < 2; t++) {
                    const int m = t ? m2 : m1;
                    const float2 v = t ? v2 : v1;
                    const int b = m >> 11, s = m & (S_LEN - 1);
                    const size_t bh = (size_t)(b * NH + hh);
                    uint32_t hi, lo;
                    if (mode == 0) {
                        size_t base = (bh * S_LEN + s) * 128 + d;
                        split2(v.x, v.y, hi, lo);
                        *reinterpret_cast<uint32_t*>(H + base)      = hi;
                        *reinterpret_cast<uint32_t*>(H + base + 64) = lo;
                    } else {  // mode 2: V transposed
                        __half hx = __float2half_rn(v.x);
                        __half hy = __float2half_rn(v.y);
                        __half lx = __float2half_rn(v.x - __half2float(hx));
                        __half ly = __float2half_rn(v.y - __half2float(hy));
                        size_t vb = bh * 128;
                        H[(vb + d)      * S_LEN + s] = hx;
                        H[(vb + d + 1)  * S_LEN + s] = hy;
                        H[(vb + 64 + d) * S_LEN + s] = lx;
                        H[(vb + 65 + d) * S_LEN + s] = ly;
                    }
                }
            }
        }
    }
}

// ======================= HMMA flash attention ==============================
// DOUBLE-BUFFERED K/V; all-finite softmax (mask/init = -60000).
// 2-PASS: QK = (Qh+Ql)xKh ; PV = (Ph+Pl)xVh.
// Hoisted cp.async pointers; incremental ALiBi ints; diagonal half-tile skip.
#define SQ_OFF  0
#define SK0_OFF 34816
#define SK1_OFF 52224
#define SV0_OFF 69632
#define SV1_OFF 88064
#define ATTN_SMEM 106496
#define L2E 1.442695040888963f
#define MNEG (-60000.0f)

__global__ __launch_bounds__(256) void attn_h_kernel(
    const __half* __restrict__ Qp, const __half* __restrict__ Kp,
    const __half* __restrict__ Vp, __half* __restrict__ AOp)
{
    extern __shared__ char smc[];
    const uint32_t sb = smem_u32(smc);
    const int tid  = threadIdx.x;
    const int lane = tid & 31;
    const int w    = tid >> 5;
    const int bh   = blockIdx.y;
    const int h    = bh & (NH - 1);
    const bool fwd = (h < 8);
    const int qb   = fwd ? (NQB - 1 - blockIdx.x) : blockIdx.x;
    const int q0   = qb * 128;
    const int sidx = fwd ? h : (h - 8);
    const float slope = exp2f(-(float)(sidx + 1) * 0.57312031259014454f);

    const __half* Qg = Qp + ((size_t)bh * S_LEN + q0) * 128;
    const __half* Kg = Kp + (size_t)bh * S_LEN * 128;
    const __half* Vg = Vp + (size_t)bh * 128 * S_LEN;

    const int kt_begin = fwd ? 0 : 2 * qb;
    const int kt_end   = fwd ? (2 * qb + 1) : (NKT - 1);
    const int ntiles   = kt_end - kt_begin + 1;

    // hoisted per-thread K/V copy addressing (advance pointers per tile)
    uint32_t koff[4], voff[4];
    const __half* ksrc[4];
    const __half* vsrc[4];
    #pragma unroll
    for (int i = 0; i < 4; i++) {
        int id = tid + i * 256;
        koff[i] = (id >> 4) * 272 + (id & 15) * 16;
        voff[i] = (id >> 3) * 144 + (id & 7) * 16;
        ksrc[i] = Kg + (size_t)(kt_begin * 64 + (id >> 4)) * 128 + (id & 15) * 8;
        vsrc[i] = Vg + (size_t)(id >> 3) * S_LEN + kt_begin * 64 + (id & 7) * 8;
    }

    // prologue: Q tile + first K/V tile (one group)
    #pragma unroll
    for (int i = 0; i < 8; i++) {
        int id = tid + i * 256;
        CP_ASYNC16(sb + SQ_OFF + (id >> 4) * 272 + (id & 15) * 16,
                   Qg + (size_t)(id >> 4) * 128 + (id & 15) * 8);
    }
    #pragma unroll
    for (int i = 0; i < 4; i++) {
        CP_ASYNC16(sb + SK0_OFF + koff[i], ksrc[i]);
        CP_ASYNC16(sb + SV0_OFF + voff[i], vsrc[i]);
    }
    CP_COMMIT();
    #pragma unroll
    for (int i = 0; i < 4; i++) { ksrc[i] += 64 * 128; vsrc[i] += 64; }
    CP_WAIT0();
    __syncthreads();

    // Q fragments into registers (kept whole kernel)
    uint32_t qh[4][4], ql[4][4];
    {
        const int arow = w * 16 + (lane & 7) + ((lane >> 3) & 1) * 8;
        const uint32_t aoff = ((lane >> 4) & 1) * 16;
        #pragma unroll
        for (int kt = 0; kt < 4; kt++) {
            uint32_t ad = sb + SQ_OFF + arow * 272 + kt * 32 + aoff;
            LDM_X4(qh[kt][0], qh[kt][1], qh[kt][2], qh[kt][3], ad);
            LDM_X4(ql[kt][0], ql[kt][1], ql[kt][2], ql[kt][3], ad + 128);
        }
    }

    float o[8][4];
    #pragma unroll
    for (int nt = 0; nt < 8; nt++)
        #pragma unroll
        for (int q = 0; q < 4; q++)
            o[nt][q] = 0.0f;

    const int g  = lane >> 2;
    const int tq = lane & 3;
    const int row0g = q0 + w * 16 + g;
    float m0 = MNEG, m1 = MNEG, l0 = 0.0f, l1 = 0.0f;

    const int brow_base = (lane & 7) + ((lane >> 4) & 1) * 8;
    const uint32_t boff = ((lane >> 3) & 1) * 16;

    const int dir  = fwd ? 1 : -1;
    const int dir8 = dir * 8;
    int dbase = dir * (kt_begin * 64 + tq * 2 - row0g);

    for (int it = 0; it < ntiles; it++) {
        const int sel = it & 1;
        if (it + 1 < ntiles) {
            const uint32_t dk = sb + ((it + 1) & 1 ? SK1_OFF : SK0_OFF);
            const uint32_t dv = sb + ((it + 1) & 1 ? SV1_OFF : SV0_OFF);
            #pragma unroll
            for (int i = 0; i < 4; i++) {
                CP_ASYNC16(dk + koff[i], ksrc[i]);
                CP_ASYNC16(dv + voff[i], vsrc[i]);
            }
            CP_COMMIT();
            #pragma unroll
            for (int i = 0; i < 4; i++) { ksrc[i] += 64 * 128; vsrc[i] += 64; }
            CP_WAIT1();
        } else {
            CP_WAIT0();
        }
        __syncthreads();

        const bool skip = fwd ? (it == ntiles - 1 && w < 4)
                              : (it == 0 && w >= 4);
        if (!skip) {
            const uint32_t KB = sb + (sel ? SK1_OFF : SK0_OFF);
            const uint32_t VB = sb + (sel ? SV1_OFF : SV0_OFF);

            // ---- S = Q K^T (2-pass: (Qh+Ql) x Kh) ----
            float sc[8][4];
            #pragma unroll
            for (int nt = 0; nt < 8; nt++)
                #pragma unroll
                for (int q = 0; q < 4; q++)
                    sc[nt][q] = 0.0f;

            #pragma unroll
            for (int kt = 0; kt < 4; kt++) {
                #pragma unroll
                for (int nt2 = 0; nt2 < 4; nt2++) {
                    uint32_t bd = KB + (nt2 * 16 + brow_base) * 272 + kt * 32 + boff;
                    uint32_t b0, b1, b2, b3;
                    LDM_X4(b0, b1, b2, b3, bd);
                    MMA16816(sc[2*nt2],   qh[kt], b0, b1);
                    MMA16816(sc[2*nt2],   ql[kt], b0, b1);
                    MMA16816(sc[2*nt2+1], qh[kt], b2, b3);
                    MMA16816(sc[2*nt2+1], ql[kt], b2, b3);
                }
            }

            // ---- ALiBi bias + online softmax (registers, all-finite) ----
            float mx0 = MNEG, mx1 = MNEG;
            int dn = dbase;
            #pragma unroll
            for (int nt = 0; nt < 8; nt++) {
                #pragma unroll
                for (int e = 0; e < 2; e++) {
                    const int d0 = dn + (e ? dir : 0);
                    const int d1 = d0 - dir8;
                    const float b0f = (d0 > 0) ? MNEG : slope * (float)d0;
                    const float b1f = (d1 > 0) ? MNEG : slope * (float)d1;
                    sc[nt][e]     += b0f;
                    sc[nt][2 + e] += b1f;
                    mx0 = fmaxf(mx0, sc[nt][e]);
                    mx1 = fmaxf(mx1, sc[nt][2 + e]);
                }
                dn += dir8;
            }
            mx0 = fmaxf(mx0, __shfl_xor_sync(0xffffffffu, mx0, 1));
            mx0 = fmaxf(mx0, __shfl_xor_sync(0xffffffffu, mx0, 2));
            mx1 = fmaxf(mx1, __shfl_xor_sync(0xffffffffu, mx1, 1));
            mx1 = fmaxf(mx1, __shfl_xor_sync(0xffffffffu, mx1, 2));
            const float mn0 = fmaxf(m0, mx0);
            const float mn1 = fmaxf(m1, mx1);
            const float corr0 = exp2f((m0 - mn0) * L2E);
            const float corr1 = exp2f((m1 - mn1) * L2E);
            const float s0 = mn0 * L2E, s1 = mn1 * L2E;
            float ls0 = 0.0f, ls1 = 0.0f;
            #pragma unroll
            for (int nt = 0; nt < 8; nt++) {
                float p0 = exp2f(fmaf(sc[nt][0], L2E, -s0));
                float p1 = exp2f(fmaf(sc[nt][1], L2E, -s0));
                float p2 = exp2f(fmaf(sc[nt][2], L2E, -s1));
                float p3 = exp2f(fmaf(sc[nt][3], L2E, -s1));
                sc[nt][0] = p0; sc[nt][1] = p1; sc[nt][2] = p2; sc[nt][3] = p3;
                ls0 += p0 + p1;
                ls1 += p2 + p3;
            }
            ls0 += __shfl_xor_sync(0xffffffffu, ls0, 1);
            ls0 += __shfl_xor_sync(0xffffffffu, ls0, 2);
            ls1 += __shfl_xor_sync(0xffffffffu, ls1, 1);
            ls1 += __shfl_xor_sync(0xffffffffu, ls1, 2);
            l0 = l0 * corr0 + ls0;
            l1 = l1 * corr1 + ls1;
            m0 = mn0;
            m1 = mn1;
            #pragma unroll
            for (int nt = 0; nt < 8; nt++) {
                o[nt][0] *= corr0; o[nt][1] *= corr0;
                o[nt][2] *= corr1; o[nt][3] *= corr1;
            }

            // ---- O += P V (2-pass: (Ph+Pl) x Vh) ----
            #pragma unroll
            for (int kt = 0; kt < 4; kt++) {
                uint32_t ah[4], al[4];
                split2(sc[2*kt][0],   sc[2*kt][1],   ah[0], al[0]);
                split2(sc[2*kt][2],   sc[2*kt][3],   ah[1], al[1]);
                split2(sc[2*kt+1][0], sc[2*kt+1][1], ah[2], al[2]);
                split2(sc[2*kt+1][2], sc[2*kt+1][3], ah[3], al[3]);
                #pragma unroll
                for (int nt2 = 0; nt2 < 4; nt2++) {
                    uint32_t vd = VB + (nt2 * 16 + brow_base) * 144 + kt * 32 + boff;
                    uint32_t b0, b1, b2, b3;
                    LDM_X4(b0, b1, b2, b3, vd);
                    MMA16816(o[2*nt2],   ah, b0, b1);
                    MMA16816(o[2*nt2],   al, b0, b1);
                    MMA16816(o[2*nt2+1], ah, b2, b3);
                    MMA16816(o[2*nt2+1], al, b2, b3);
                }
            }
        }
        dbase += dir * 64;
        __syncthreads();
    }

    // ---- epilogue: O /= l, write packed hi/lo into AOp (PK layout) ----
    const float inv0 = 1.0f / l0;
    const float inv1 = 1.0f / l1;
    const int bi = bh >> 4;
    const size_t ar0 = (size_t)(bi * S_LEN) + row0g;
    #pragma unroll
    for (int nt = 0; nt < 8; nt++) {
        const int cc = h * HD + nt * 8 + tq * 2;
        const size_t coff = (size_t)(cc >> 4) * 32 + (cc & 15);
        uint32_t hi, lo;
        split2(o[nt][0] * inv0, o[nt][1] * inv0, hi, lo);
        *reinterpret_cast<uint32_t*>(AOp + ar0 * PK + coff)      = hi;
        *reinterpret_cast<uint32_t*>(AOp + ar0 * PK + coff + 16) = lo;
        split2(o[nt][2] * inv1, o[nt][3] * inv1, hi, lo);
        *reinterpret_cast<uint32_t*>(AOp + (ar0 + 8) * PK + coff)      = hi;
        *reinterpret_cast<uint32_t*>(AOp + (ar0 + 8) * PK + coff + 16) = lo;
    }
}

// ---------------------------------------------------------------------------
extern "C" void kernel_launch(void* const* d_in, const int* in_sizes, int n_in,
                              void* d_out, int out_size)
{
    const float* query = (const float*)d_in[0];
    const float* key_i = (const float*)d_in[1];
    const float* value = (const float*)d_in[2];
    const float* Wq = (const float*)d_in[3];
    const float* bq = (const float*)d_in[4];
    const float* Wk = (const float*)d_in[5];
    const float* bk = (const float*)d_in[6];
    const float* Wv = (const float*)d_in[7];
    const float* bv = (const float*)d_in[8];
    const float* Wo = (const float*)d_in[9];
    const float* bo = (const float*)d_in[10];
    float* out = (float*)d_out;

    __half* hb = nullptr;
    cudaGetSymbolAddress((void**)&hb, g_h16);
    __half* AQ  = hb + HP_AQ;
    __half* AK  = hb + HP_AK;
    __half* AV  = hb + HP_AV;
    __half* AOp = hb + HP_AOP;
    __half* Wqp = hb + HP_W0;
    __half* Wkp = Wqp + HP_WSZ;
    __half* Wvp = Wkp + HP_WSZ;
    __half* Wop = Wvp + HP_WSZ;
    __half* QH  = hb + HP_QH;
    __half* KH  = hb + HP_KH;
    __half* VH  = hb + HP_VH;

    cudaFuncSetAttribute(hgemm_split_kernel,
                         cudaFuncAttributeMaxDynamicSharedMemorySize, GEMM_SMEM);
    cudaFuncSetAttribute(attn_h_kernel,
                         cudaFuncAttributeMaxDynamicSharedMemorySize, ATTN_SMEM);

    const int n4_in = M_ROWS * (KDIM / 4);
    const int n4_w  = MODEL * (KDIM / 4);

    // merged cvt: inputs (3 jobs), weights (4 jobs)
    {
        CvtPair pi0{query, AQ}, pi1{key_i, AK}, pi2{value, AV};
        cvt_multi_kernel<<<dim3(n4_in / 256, 3), 256>>>(pi0, pi1, pi2, pi0, n4_in);
        CvtPair pw0{Wq, Wqp}, pw1{Wk, Wkp}, pw2{Wv, Wvp}, pw3{Wo, Wop};
        cvt_multi_kernel<<<dim3(n4_w / 256, 4), 256>>>(pw0, pw1, pw2, pw3, n4_w);
    }

    // merged Q/K/V projection GEMMs (one launch, z selects job)
    GJob jq{AQ, Wqp, bq, QH, 0, 0.125f};
    GJob jk{AK, Wkp, bk, KH, 0, 1.0f};
    GJob jv{AV, Wvp, bv, VH, 2, 1.0f};
    hgemm_split_kernel<<<dim3(MODEL / 128, M_ROWS / 128, 3), 256, GEMM_SMEM>>>(jq, jk, jv);

    dim3 ga(NQB, B_SZ * NH);                 // (16, 64)
    attn_h_kernel<<<ga, 256, ATTN_SMEM>>>(QH, KH, VH, AOp);

    GJob jo{AOp, Wop, bo, out, 1, 1.0f};
    hgemm_split_kernel<<<dim3(MODEL / 128, M_ROWS / 128, 1), 256, GEMM_SMEM>>>(jo, jo, jo);
}

// round 14
// speedup vs baseline: 1.0261x; 1.0261x over previous
#include <cuda_runtime.h>
#include <cuda_fp16.h>
#include <cstdint>

#define B_SZ   4
#define S_LEN  2048
#define NH     16
#define HD     64
#define MODEL  1024
#define KDIM   1024
#define M_ROWS 8192
#define PK     2048      // packed halves per row (hi16|lo16 interleave per 16 elems)
#define NQB    16
#define NKT    32

// ---- packed fp16 scratch layout (halves) ----
#define HP_AQ  0ull
#define HP_AK  (1ull * M_ROWS * PK)
#define HP_AV  (2ull * M_ROWS * PK)
#define HP_AOP (3ull * M_ROWS * PK)
#define HP_WSZ ((unsigned long long)MODEL * PK)
#define HP_W0  (4ull * M_ROWS * PK)
#define BH_SZ  (64ull * S_LEN * 128)
#define HP_QH  (HP_W0 + 4ull * HP_WSZ)
#define HP_KH  (HP_QH + BH_SZ)
#define HP_VH  (HP_KH + BH_SZ)
__device__ __half g_h16[HP_VH + BH_SZ];

// ============================ helpers ======================================
__device__ __forceinline__ uint32_t smem_u32(const void* p) {
    uint32_t a;
    asm("{ .reg .u64 t; cvta.to.shared.u64 t, %1; cvt.u32.u64 %0, t; }"
        : "=r"(a) : "l"(p));
    return a;
}

// split pair of floats into packed hi half2 + lo half2
__device__ __forceinline__ void split2(float x, float y, uint32_t& hi, uint32_t& lo) {
    __half2 h = __floats2half2_rn(x, y);
    float2 f = __half22float2(h);
    __half2 l = __floats2half2_rn(x - f.x, y - f.y);
    hi = *reinterpret_cast<uint32_t*>(&h);
    lo = *reinterpret_cast<uint32_t*>(&l);
}

#define CP_ASYNC16(dst, src) \
    asm volatile("cp.async.cg.shared.global [%0], [%1], 16;" :: "r"(dst), "l"(src))
#define CP_COMMIT() asm volatile("cp.async.commit_group;")
#define CP_WAIT1()  asm volatile("cp.async.wait_group 1;")
#define CP_WAIT0()  asm volatile("cp.async.wait_group 0;")

#define LDM_X4(r0, r1, r2, r3, addr) \
    asm volatile("ldmatrix.sync.aligned.m8n8.x4.shared.b16 {%0,%1,%2,%3}, [%4];" \
                 : "=r"(r0), "=r"(r1), "=r"(r2), "=r"(r3) : "r"(addr))

#define MMA16816(c, a, b0, b1) \
    asm volatile("mma.sync.aligned.m16n8k16.row.col.f32.f16.f16.f32 " \
                 "{%0,%1,%2,%3}, {%4,%5,%6,%7}, {%8,%9}, {%0,%1,%2,%3};" \
                 : "+f"((c)[0]), "+f"((c)[1]), "+f"((c)[2]), "+f"((c)[3]) \
                 : "r"((a)[0]), "r"((a)[1]), "r"((a)[2]), "r"((a)[3]), \
                   "r"(b0), "r"(b1))

// ============================ split-convert prepass ========================
struct CvtPair { const float* s; __half* d; };

__global__ __launch_bounds__(256) void cvt_multi_kernel(
    CvtPair p0, CvtPair p1, CvtPair p2, CvtPair p3, int n4)
{
    CvtPair p = (blockIdx.y == 0) ? p0 : (blockIdx.y == 1) ? p1
              : (blockIdx.y == 2) ? p2 : p3;
    int i = blockIdx.x * blockDim.x + threadIdx.x;
    if (i >= n4) return;
    float4 v = reinterpret_cast<const float4*>(p.s)[i];
    int row  = i >> 8;
    int kpos = (i & 255) << 2;
    size_t base = (size_t)row * PK + (size_t)(kpos >> 4) * 32 + (kpos & 15);
    uint32_t h0, l0, h1, l1;
    split2(v.x, v.y, h0, l0);
    split2(v.z, v.w, h1, l1);
    *reinterpret_cast<uint2*>(p.d + base)      = make_uint2(h0, h1);
    *reinterpret_cast<uint2*>(p.d + base + 16) = make_uint2(l0, l1);
}

// ============================ fp16-split HMMA GEMM =========================
// C = A @ W^T + bias.  CTA tile 128x128, 8 warps (64x32 warp tile), K staged
// 32, 2-stage cp.async pipeline.  2-PASS: (Ah+Al) x Wh.
// __launch_bounds__(256, 2): 2 CTAs/SM (R12 winner form — R13 variant reverted).
// gridDim.z selects one of up to 3 jobs (merged launches).
// mode 0: packed QK attn layout [bh][s][hi64|lo64] (scaled by oscale)
// mode 1: fp32 row-major [M,1024]
// mode 2: packed V transposed [bh][hi-d 0..63, lo-d 64..127][s]
struct GJob {
    const __half* A;
    const __half* W;
    const float*  bias;
    void*         C;
    int           mode;
    float         oscale;
};

#define GR 144
#define STAGE_BYTES (2 * 128 * GR)  // A tile + B tile = 36864
#define GEMM_SMEM (2 * STAGE_BYTES) // 73728

__global__ __launch_bounds__(256, 2) void hgemm_split_kernel(GJob j0, GJob j1, GJob j2)
{
    const GJob J = (blockIdx.z == 0) ? j0 : (blockIdx.z == 1) ? j1 : j2;
    const __half* Ap = J.A;
    const __half* Wp = J.W;
    const float* bias = J.bias;
    void* Cv = J.C;
    const int mode = J.mode;
    const float oscale = J.oscale;

    extern __shared__ char smem[];
    const uint32_t sb = smem_u32(smem);
    const int tid  = threadIdx.x;
    const int lane = tid & 31;
    const int wid  = tid >> 5;
    const int wm   = wid & 1;        // 2 warp-rows x 64
    const int wn   = wid >> 1;       // 4 warp-cols x 32

    const int row0 = blockIdx.y * 128;
    const int col0 = blockIdx.x * 128;

    const int lrow = tid >> 1;
    const int lhalf = (tid & 1) * 4;
    const __half* Ag = Ap + (size_t)(row0 + lrow) * PK + lhalf * 8;
    const __half* Wg = Wp + (size_t)(col0 + lrow) * PK + lhalf * 8;
    const uint32_t sA = sb + lrow * GR + lhalf * 16;
    const uint32_t sB = sA + 128 * GR;

    float c[4][4][4];
    #pragma unroll
    for (int mt = 0; mt < 4; mt++)
        #pragma unroll
        for (int nt = 0; nt < 4; nt++)
            #pragma unroll
            for (int q = 0; q < 4; q++)
                c[mt][nt][q] = 0.0f;

    const int arow = wm * 64 + (lane & 7) + ((lane >> 3) & 1) * 8;
    const uint32_t aoff = ((lane >> 4) & 1) * 16;
    const int brow = wn * 32 + (lane & 7) + ((lane >> 4) & 1) * 8;
    const uint32_t boff = ((lane >> 3) & 1) * 16;

    #pragma unroll
    for (int i = 0; i < 4; i++) {
        CP_ASYNC16(sA + i * 16, Ag + i * 8);
        CP_ASYNC16(sB + i * 16, Wg + i * 8);
    }
    CP_COMMIT();

    const int NSTAGE = KDIM / 32;
    for (int s = 0; s < NSTAGE; s++) {
        const int sel = s & 1;
        if (s + 1 < NSTAGE) {
            const int nsel = (s + 1) & 1;
            const __half* Agn = Ag + (size_t)(s + 1) * 64;
            const __half* Wgn = Wg + (size_t)(s + 1) * 64;
            #pragma unroll
            for (int i = 0; i < 4; i++) {
                CP_ASYNC16(sA + nsel * STAGE_BYTES + i * 16, Agn + i * 8);
                CP_ASYNC16(sB + nsel * STAGE_BYTES + i * 16, Wgn + i * 8);
            }
            CP_COMMIT();
            CP_WAIT1();
        } else {
            CP_WAIT0();
        }
        __syncthreads();

        const uint32_t Abase = sb + sel * STAGE_BYTES;
        const uint32_t Bbase = Abase + 128 * GR;

        #pragma unroll
        for (int kk = 0; kk < 2; kk++) {
            uint32_t aH[4][4], aL[4][4], bH[8];
            const uint32_t gH = kk * 2, gL = kk * 2 + 1;
            #pragma unroll
            for (int mt = 0; mt < 4; mt++) {
                uint32_t ad = Abase + (arow + mt * 16) * GR + aoff;
                LDM_X4(aH[mt][0], aH[mt][1], aH[mt][2], aH[mt][3], ad + gH * 32);
                LDM_X4(aL[mt][0], aL[mt][1], aL[mt][2], aL[mt][3], ad + gL * 32);
            }
            #pragma unroll
            for (int nt2 = 0; nt2 < 2; nt2++) {
                uint32_t bd = Bbase + (brow + nt2 * 16) * GR + boff;
                LDM_X4(bH[nt2*4+0], bH[nt2*4+1], bH[nt2*4+2], bH[nt2*4+3], bd + gH * 32);
            }
            #pragma unroll
            for (int mt = 0; mt < 4; mt++)
                #pragma unroll
                for (int nt = 0; nt < 4; nt++) {
                    MMA16816(c[mt][nt], aH[mt], bH[nt*2], bH[nt*2+1]);
                    MMA16816(c[mt][nt], aL[mt], bH[nt*2], bH[nt*2+1]);
                }
        }
        __syncthreads();
    }

    const int mrow0 = row0 + wm * 64;
    const int ncol0 = col0 + wn * 32;
    #pragma unroll
    for (int mt = 0; mt < 4; mt++) {
        #pragma unroll
        for (int nt = 0; nt < 4; nt++) {
            const int n = ncol0 + nt * 8 + (lane & 3) * 2;
            const float2 bv = *reinterpret_cast<const float2*>(bias + n);
            const int m1 = mrow0 + mt * 16 + (lane >> 2);
            const int m2 = m1 + 8;
            float2 v1 = make_float2((c[mt][nt][0] + bv.x) * oscale,
                                    (c[mt][nt][1] + bv.y) * oscale);
            float2 v2 = make_float2((c[mt][nt][2] + bv.x) * oscale,
                                    (c[mt][nt][3] + bv.y) * oscale);
            if (mode == 1) {
                float* C = (float*)Cv;
                *reinterpret_cast<float2*>(C + (size_t)m1 * MODEL + n) = v1;
                *reinterpret_cast<float2*>(C + (size_t)m2 * MODEL + n) = v2;
            } else {
                __half* H = (__half*)Cv;
                const int hh = n >> 6, d = n & (HD - 1);
                #pragma unroll
                for (int t = 0; t < 2; t++) {
                    const int m = t ? m2 : m1;
                    const float2 v = t ? v2 : v1;
                    const int b = m >> 11, s = m & (S_LEN - 1);
                    const size_t bh = (size_t)(b * NH + hh);
                    uint32_t hi, lo;
                    if (mode == 0) {
                        size_t base = (bh * S_LEN + s) * 128 + d;
                        split2(v.x, v.y, hi, lo);
                        *reinterpret_cast<uint32_t*>(H + base)      = hi;
                        *reinterpret_cast<uint32_t*>(H + base + 64) = lo;
                    } else {  // mode 2: V transposed
                        __half hx = __float2half_rn(v.x);
                        __half hy = __float2half_rn(v.y);
                        __half lx = __float2half_rn(v.x - __half2float(hx));
                        __half ly = __float2half_rn(v.y - __half2float(hy));
                        size_t vb = bh * 128;
                        H[(vb + d)      * S_LEN + s] = hx;
                        H[(vb + d + 1)  * S_LEN + s] = hy;
                        H[(vb + 64 + d) * S_LEN + s] = lx;
                        H[(vb + 65 + d) * S_LEN + s] = ly;
                    }
                }
            }
        }
    }
}

// ======================= HMMA flash attention ==============================
// R14: __launch_bounds__(256, 2) for 2 CTAs/SM.  Register diet: Q fragments
// reloaded per-kt from retained Q smem (not persistent); K/V prefetch
// addressing computed inline per tile (no persistent pointer arrays).
// DOUBLE-BUFFERED K/V; all-finite softmax; 2-PASS QK and PV; diag skip.
#define SQ_OFF  0
#define SK0_OFF 34816
#define SK1_OFF 52224
#define SV0_OFF 69632
#define SV1_OFF 88064
#define ATTN_SMEM 106496
#define L2E 1.442695040888963f
#define MNEG (-60000.0f)

__global__ __launch_bounds__(256, 2) void attn_h_kernel(
    const __half* __restrict__ Qp, const __half* __restrict__ Kp,
    const __half* __restrict__ Vp, __half* __restrict__ AOp)
{
    extern __shared__ char smc[];
    const uint32_t sb = smem_u32(smc);
    const int tid  = threadIdx.x;
    const int lane = tid & 31;
    const int w    = tid >> 5;
    const int bh   = blockIdx.y;
    const int h    = bh & (NH - 1);
    const bool fwd = (h < 8);
    const int qb   = fwd ? (NQB - 1 - blockIdx.x) : blockIdx.x;
    const int q0   = qb * 128;
    const int sidx = fwd ? h : (h - 8);
    const float slope = exp2f(-(float)(sidx + 1) * 0.57312031259014454f);

    const __half* Qg = Qp + ((size_t)bh * S_LEN + q0) * 128;
    const __half* Kg = Kp + (size_t)bh * S_LEN * 128;
    const __half* Vg = Vp + (size_t)bh * 128 * S_LEN;

    const int kt_begin = fwd ? 0 : 2 * qb;
    const int kt_end   = fwd ? (2 * qb + 1) : (NKT - 1);
    const int ntiles   = kt_end - kt_begin + 1;

    // prologue: Q tile + first K/V tile (one group); addressing inline
    #pragma unroll
    for (int i = 0; i < 8; i++) {
        int id = tid + i * 256;
        CP_ASYNC16(sb + SQ_OFF + (id >> 4) * 272 + (id & 15) * 16,
                   Qg + (size_t)(id >> 4) * 128 + (id & 15) * 8);
    }
    {
        const int k0 = kt_begin * 64;
        #pragma unroll
        for (int i = 0; i < 4; i++) {
            int id = tid + i * 256;
            CP_ASYNC16(sb + SK0_OFF + (id >> 4) * 272 + (id & 15) * 16,
                       Kg + (size_t)(k0 + (id >> 4)) * 128 + (id & 15) * 8);
            CP_ASYNC16(sb + SV0_OFF + (id >> 3) * 144 + (id & 7) * 16,
                       Vg + (size_t)(id >> 3) * S_LEN + k0 + (id & 7) * 8);
        }
    }
    CP_COMMIT();
    CP_WAIT0();
    __syncthreads();

    float o[8][4];
    #pragma unroll
    for (int nt = 0; nt < 8; nt++)
        #pragma unroll
        for (int q = 0; q < 4; q++)
            o[nt][q] = 0.0f;

    const int g  = lane >> 2;
    const int tq = lane & 3;
    const int row0g = q0 + w * 16 + g;
    float m0 = MNEG, m1 = MNEG, l0 = 0.0f, l1 = 0.0f;

    const int  arow = w * 16 + (lane & 7) + ((lane >> 3) & 1) * 8;
    const uint32_t aoff = ((lane >> 4) & 1) * 16;
    const int brow_base = (lane & 7) + ((lane >> 4) & 1) * 8;
    const uint32_t boff = ((lane >> 3) & 1) * 16;

    const int dir  = fwd ? 1 : -1;
    const int dir8 = dir * 8;
    int dbase = dir * (kt_begin * 64 + tq * 2 - row0g);

    for (int it = 0; it < ntiles; it++) {
        const int sel = it & 1;
        if (it + 1 < ntiles) {
            const int nk0 = (kt_begin + it + 1) * 64;
            const uint32_t dk = sb + (((it + 1) & 1) ? SK1_OFF : SK0_OFF);
            const uint32_t dv = sb + (((it + 1) & 1) ? SV1_OFF : SV0_OFF);
            #pragma unroll
            for (int i = 0; i < 4; i++) {
                int id = tid + i * 256;
                CP_ASYNC16(dk + (id >> 4) * 272 + (id & 15) * 16,
                           Kg + (size_t)(nk0 + (id >> 4)) * 128 + (id & 15) * 8);
                CP_ASYNC16(dv + (id >> 3) * 144 + (id & 7) * 16,
                           Vg + (size_t)(id >> 3) * S_LEN + nk0 + (id & 7) * 8);
            }
            CP_COMMIT();
            CP_WAIT1();
        } else {
            CP_WAIT0();
        }
        __syncthreads();

        const bool skip = fwd ? (it == ntiles - 1 && w < 4)
                              : (it == 0 && w >= 4);
        if (!skip) {
            const uint32_t KB = sb + (sel ? SK1_OFF : SK0_OFF);
            const uint32_t VB = sb + (sel ? SV1_OFF : SV0_OFF);

            // ---- S = Q K^T (2-pass; Q frags reloaded per-kt from smem) ----
            float sc[8][4];
            #pragma unroll
            for (int nt = 0; nt < 8; nt++)
                #pragma unroll
                for (int q = 0; q < 4; q++)
                    sc[nt][q] = 0.0f;

            #pragma unroll
            for (int kt = 0; kt < 4; kt++) {
                uint32_t qh[4], ql[4];
                uint32_t qad = sb + SQ_OFF + arow * 272 + kt * 32 + aoff;
                LDM_X4(qh[0], qh[1], qh[2], qh[3], qad);
                LDM_X4(ql[0], ql[1], ql[2], ql[3], qad + 128);
                #pragma unroll
                for (int nt2 = 0; nt2 < 4; nt2++) {
                    uint32_t bd = KB + (nt2 * 16 + brow_base) * 272 + kt * 32 + boff;
                    uint32_t b0, b1, b2, b3;
                    LDM_X4(b0, b1, b2, b3, bd);
                    MMA16816(sc[2*nt2],   qh, b0, b1);
                    MMA16816(sc[2*nt2],   ql, b0, b1);
                    MMA16816(sc[2*nt2+1], qh, b2, b3);
                    MMA16816(sc[2*nt2+1], ql, b2, b3);
                }
            }

            // ---- ALiBi bias + online softmax (registers, all-finite) ----
            float mx0 = MNEG, mx1 = MNEG;
            int dn = dbase;
            #pragma unroll
            for (int nt = 0; nt < 8; nt++) {
                #pragma unroll
                for (int e = 0; e < 2; e++) {
                    const int d0 = dn + (e ? dir : 0);
                    const int d1 = d0 - dir8;
                    const float b0f = (d0 > 0) ? MNEG : slope * (float)d0;
                    const float b1f = (d1 > 0) ? MNEG : slope * (float)d1;
                    sc[nt][e]     += b0f;
                    sc[nt][2 + e] += b1f;
                    mx0 = fmaxf(mx0, sc[nt][e]);
                    mx1 = fmaxf(mx1, sc[nt][2 + e]);
                }
                dn += dir8;
            }
            mx0 = fmaxf(mx0, __shfl_xor_sync(0xffffffffu, mx0, 1));
            mx0 = fmaxf(mx0, __shfl_xor_sync(0xffffffffu, mx0, 2));
            mx1 = fmaxf(mx1, __shfl_xor_sync(0xffffffffu, mx1, 1));
            mx1 = fmaxf(mx1, __shfl_xor_sync(0xffffffffu, mx1, 2));
            const float mn0 = fmaxf(m0, mx0);
            const float mn1 = fmaxf(m1, mx1);
            const float corr0 = exp2f((m0 - mn0) * L2E);
            const float corr1 = exp2f((m1 - mn1) * L2E);
            const float s0 = mn0 * L2E, s1 = mn1 * L2E;
            float ls0 = 0.0f, ls1 = 0.0f;
            #pragma unroll
            for (int nt = 0; nt < 8; nt++) {
                float p0 = exp2f(fmaf(sc[nt][0], L2E, -s0));
                float p1 = exp2f(fmaf(sc[nt][1], L2E, -s0));
                float p2 = exp2f(fmaf(sc[nt][2], L2E, -s1));
                float p3 = exp2f(fmaf(sc[nt][3], L2E, -s1));
                sc[nt][0] = p0; sc[nt][1] = p1; sc[nt][2] = p2; sc[nt][3] = p3;
                ls0 += p0 + p1;
                ls1 += p2 + p3;
            }
            ls0 += __shfl_xor_sync(0xffffffffu, ls0, 1);
            ls0 += __shfl_xor_sync(0xffffffffu, ls0, 2);
            ls1 += __shfl_xor_sync(0xffffffffu, ls1, 1);
            ls1 += __shfl_xor_sync(0xffffffffu, ls1, 2);
            l0 = l0 * corr0 + ls0;
            l1 = l1 * corr1 + ls1;
            m0 = mn0;
            m1 = mn1;
            #pragma unroll
            for (int nt = 0; nt < 8; nt++) {
                o[nt][0] *= corr0; o[nt][1] *= corr0;
                o[nt][2] *= corr1; o[nt][3] *= corr1;
            }

            // ---- O += P V (2-pass: (Ph+Pl) x Vh) ----
            #pragma unroll
            for (int kt = 0; kt < 4; kt++) {
                uint32_t ah[4], al[4];
                split2(sc[2*kt][0],   sc[2*kt][1],   ah[0], al[0]);
                split2(sc[2*kt][2],   sc[2*kt][3],   ah[1], al[1]);
                split2(sc[2*kt+1][0], sc[2*kt+1][1], ah[2], al[2]);
                split2(sc[2*kt+1][2], sc[2*kt+1][3], ah[3], al[3]);
                #pragma unroll
                for (int nt2 = 0; nt2 < 4; nt2++) {
                    uint32_t vd = VB + (nt2 * 16 + brow_base) * 144 + kt * 32 + boff;
                    uint32_t b0, b1, b2, b3;
                    LDM_X4(b0, b1, b2, b3, vd);
                    MMA16816(o[2*nt2],   ah, b0, b1);
                    MMA16816(o[2*nt2],   al, b0, b1);
                    MMA16816(o[2*nt2+1], ah, b2, b3);
                    MMA16816(o[2*nt2+1], al, b2, b3);
                }
            }
        }
        dbase += dir * 64;
        __syncthreads();
    }

    // ---- epilogue: O /= l, write packed hi/lo into AOp (PK layout) ----
    const float inv0 = 1.0f / l0;
    const float inv1 = 1.0f / l1;
    const int bi = bh >> 4;
    const size_t ar0 = (size_t)(bi * S_LEN) + row0g;
    #pragma unroll
    for (int nt = 0; nt < 8; nt++) {
        const int cc = h * HD + nt * 8 + tq * 2;
        const size_t coff = (size_t)(cc >> 4) * 32 + (cc & 15);
        uint32_t hi, lo;
        split2(o[nt][0] * inv0, o[nt][1] * inv0, hi, lo);
        *reinterpret_cast<uint32_t*>(AOp + ar0 * PK + coff)      = hi;
        *reinterpret_cast<uint32_t*>(AOp + ar0 * PK + coff + 16) = lo;
        split2(o[nt][2] * inv1, o[nt][3] * inv1, hi, lo);
        *reinterpret_cast<uint32_t*>(AOp + (ar0 + 8) * PK + coff)      = hi;
        *reinterpret_cast<uint32_t*>(AOp + (ar0 + 8) * PK + coff + 16) = lo;
    }
}

// ---------------------------------------------------------------------------
extern "C" void kernel_launch(void* const* d_in, const int* in_sizes, int n_in,
                              void* d_out, int out_size)
{
    const float* query = (const float*)d_in[0];
    const float* key_i = (const float*)d_in[1];
    const float* value = (const float*)d_in[2];
    const float* Wq = (const float*)d_in[3];
    const float* bq = (const float*)d_in[4];
    const float* Wk = (const float*)d_in[5];
    const float* bk = (const float*)d_in[6];
    const float* Wv = (const float*)d_in[7];
    const float* bv = (const float*)d_in[8];
    const float* Wo = (const float*)d_in[9];
    const float* bo = (const float*)d_in[10];
    float* out = (float*)d_out;

    __half* hb = nullptr;
    cudaGetSymbolAddress((void**)&hb, g_h16);
    __half* AQ  = hb + HP_AQ;
    __half* AK  = hb + HP_AK;
    __half* AV  = hb + HP_AV;
    __half* AOp = hb + HP_AOP;
    __half* Wqp = hb + HP_W0;
    __half* Wkp = Wqp + HP_WSZ;
    __half* Wvp = Wkp + HP_WSZ;
    __half* Wop = Wvp + HP_WSZ;
    __half* QH  = hb + HP_QH;
    __half* KH  = hb + HP_KH;
    __half* VH  = hb + HP_VH;

    cudaFuncSetAttribute(hgemm_split_kernel,
                         cudaFuncAttributeMaxDynamicSharedMemorySize, GEMM_SMEM);
    cudaFuncSetAttribute(attn_h_kernel,
                         cudaFuncAttributeMaxDynamicSharedMemorySize, ATTN_SMEM);

    const int n4_in = M_ROWS * (KDIM / 4);
    const int n4_w  = MODEL * (KDIM / 4);

    // merged cvt: inputs (3 jobs), weights (4 jobs)
    {
        CvtPair pi0{query, AQ}, pi1{key_i, AK}, pi2{value, AV};
        cvt_multi_kernel<<<dim3(n4_in / 256, 3), 256>>>(pi0, pi1, pi2, pi0, n4_in);
        CvtPair pw0{Wq, Wqp}, pw1{Wk, Wkp}, pw2{Wv, Wvp}, pw3{Wo, Wop};
        cvt_multi_kernel<<<dim3(n4_w / 256, 4), 256>>>(pw0, pw1, pw2, pw3, n4_w);
    }

    // merged Q/K/V projection GEMMs (one launch, z selects job)
    GJob jq{AQ, Wqp, bq, QH, 0, 0.125f};
    GJob jk{AK, Wkp, bk, KH, 0, 1.0f};
    GJob jv{AV, Wvp, bv, VH, 2, 1.0f};
    hgemm_split_kernel<<<dim3(MODEL / 128, M_ROWS / 128, 3), 256, GEMM_SMEM>>>(jq, jk, jv);

    dim3 ga(NQB, B_SZ * NH);                 // (16, 64)
    attn_h_kernel<<<ga, 256, ATTN_SMEM>>>(QH, KH, VH, AOp);

    GJob jo{AOp, Wop, bo, out, 1, 1.0f};
    hgemm_split_kernel<<<dim3(MODEL / 128, M_ROWS / 128, 1), 256, GEMM_SMEM>>>(jo, jo, jo);
}

// round 15
// speedup vs baseline: 1.0498x; 1.0231x over previous
#include <cuda_runtime.h>
#include <cuda_fp16.h>
#include <cstdint>

#define B_SZ   4
#define S_LEN  2048
#define NH     16
#define HD     64
#define MODEL  1024
#define KDIM   1024
#define M_ROWS 8192
#define PK     2048      // packed halves per row (hi16|lo16 interleave per 16 elems)
#define NQB    16
#define NKT    32

// ---- packed fp16 scratch layout (halves) ----
#define HP_AQ  0ull
#define HP_AK  (1ull * M_ROWS * PK)
#define HP_AV  (2ull * M_ROWS * PK)
#define HP_AOP (3ull * M_ROWS * PK)
#define HP_WSZ ((unsigned long long)MODEL * PK)
#define HP_W0  (4ull * M_ROWS * PK)
#define BH_SZ  (64ull * S_LEN * 128)
#define HP_QH  (HP_W0 + 4ull * HP_WSZ)
#define HP_KH  (HP_QH + BH_SZ)
#define HP_VH  (HP_KH + BH_SZ)
__device__ __half g_h16[HP_VH + BH_SZ];

// ============================ helpers ======================================
__device__ __forceinline__ uint32_t smem_u32(const void* p) {
    uint32_t a;
    asm("{ .reg .u64 t; cvta.to.shared.u64 t, %1; cvt.u32.u64 %0, t; }"
        : "=r"(a) : "l"(p));
    return a;
}

// split pair of floats into packed hi half2 + lo half2
__device__ __forceinline__ void split2(float x, float y, uint32_t& hi, uint32_t& lo) {
    __half2 h = __floats2half2_rn(x, y);
    float2 f = __half22float2(h);
    __half2 l = __floats2half2_rn(x - f.x, y - f.y);
    hi = *reinterpret_cast<uint32_t*>(&h);
    lo = *reinterpret_cast<uint32_t*>(&l);
}

#define CP_ASYNC16(dst, src) \
    asm volatile("cp.async.cg.shared.global [%0], [%1], 16;" :: "r"(dst), "l"(src))
#define CP_COMMIT() asm volatile("cp.async.commit_group;")
#define CP_WAIT1()  asm volatile("cp.async.wait_group 1;")
#define CP_WAIT0()  asm volatile("cp.async.wait_group 0;")

#define LDM_X4(r0, r1, r2, r3, addr) \
    asm volatile("ldmatrix.sync.aligned.m8n8.x4.shared.b16 {%0,%1,%2,%3}, [%4];" \
                 : "=r"(r0), "=r"(r1), "=r"(r2), "=r"(r3) : "r"(addr))

#define MMA16816(c, a, b0, b1) \
    asm volatile("mma.sync.aligned.m16n8k16.row.col.f32.f16.f16.f32 " \
                 "{%0,%1,%2,%3}, {%4,%5,%6,%7}, {%8,%9}, {%0,%1,%2,%3};" \
                 : "+f"((c)[0]), "+f"((c)[1]), "+f"((c)[2]), "+f"((c)[3]) \
                 : "r"((a)[0]), "r"((a)[1]), "r"((a)[2]), "r"((a)[3]), \
                   "r"(b0), "r"(b1))

// ============================ split-convert prepass ========================
struct CvtPair { const float* s; __half* d; };

__global__ __launch_bounds__(256) void cvt_multi_kernel(
    CvtPair p0, CvtPair p1, CvtPair p2, CvtPair p3, int n4)
{
    CvtPair p = (blockIdx.y == 0) ? p0 : (blockIdx.y == 1) ? p1
              : (blockIdx.y == 2) ? p2 : p3;
    int i = blockIdx.x * blockDim.x + threadIdx.x;
    if (i >= n4) return;
    float4 v = reinterpret_cast<const float4*>(p.s)[i];
    int row  = i >> 8;
    int kpos = (i & 255) << 2;
    size_t base = (size_t)row * PK + (size_t)(kpos >> 4) * 32 + (kpos & 15);
    uint32_t h0, l0, h1, l1;
    split2(v.x, v.y, h0, l0);
    split2(v.z, v.w, h1, l1);
    *reinterpret_cast<uint2*>(p.d + base)      = make_uint2(h0, h1);
    *reinterpret_cast<uint2*>(p.d + base + 16) = make_uint2(l0, l1);
}

// ============================ fp16-split HMMA GEMM =========================
// C = A @ W^T + bias.  CTA tile 128x128, 8 warps (64x32 warp tile).
// R15: 3-STAGE cp.async ring, ONE __syncthreads per K-stage (32 barriers
// instead of 64), prefetch depth 2.  2-PASS: (Ah+Al) x Wh.
// __launch_bounds__(256, 2): 2 CTAs/SM (3*36864=110592B <= 116736B budget).
// gridDim.z selects one of up to 3 jobs (merged launches).
// mode 0: packed QK attn layout [bh][s][hi64|lo64] (scaled by oscale)
// mode 1: fp32 row-major [M,1024]
// mode 2: packed V transposed [bh][hi-d 0..63, lo-d 64..127][s]
struct GJob {
    const __half* A;
    const __half* W;
    const float*  bias;
    void*         C;
    int           mode;
    float         oscale;
};

#define GR 144
#define STAGE_BYTES (2 * 128 * GR)  // A tile + B tile = 36864
#define GEMM_SMEM (3 * STAGE_BYTES) // 110592

__global__ __launch_bounds__(256, 2) void hgemm_split_kernel(GJob j0, GJob j1, GJob j2)
{
    const GJob J = (blockIdx.z == 0) ? j0 : (blockIdx.z == 1) ? j1 : j2;
    const __half* Ap = J.A;
    const __half* Wp = J.W;
    const float* bias = J.bias;
    void* Cv = J.C;
    const int mode = J.mode;
    const float oscale = J.oscale;

    extern __shared__ char smem[];
    const uint32_t sb = smem_u32(smem);
    const int tid  = threadIdx.x;
    const int lane = tid & 31;
    const int wid  = tid >> 5;
    const int wm   = wid & 1;        // 2 warp-rows x 64
    const int wn   = wid >> 1;       // 4 warp-cols x 32

    const int row0 = blockIdx.y * 128;
    const int col0 = blockIdx.x * 128;

    const int lrow = tid >> 1;
    const int lhalf = (tid & 1) * 4;
    const __half* Ag = Ap + (size_t)(row0 + lrow) * PK + lhalf * 8;
    const __half* Wg = Wp + (size_t)(col0 + lrow) * PK + lhalf * 8;
    const uint32_t sA = sb + lrow * GR + lhalf * 16;
    const uint32_t sB = sA + 128 * GR;

    float c[4][4][4];
    #pragma unroll
    for (int mt = 0; mt < 4; mt++)
        #pragma unroll
        for (int nt = 0; nt < 4; nt++)
            #pragma unroll
            for (int q = 0; q < 4; q++)
                c[mt][nt][q] = 0.0f;

    const int arow = wm * 64 + (lane & 7) + ((lane >> 3) & 1) * 8;
    const uint32_t aoff = ((lane >> 4) & 1) * 16;
    const int brow = wn * 32 + (lane & 7) + ((lane >> 4) & 1) * 8;
    const uint32_t boff = ((lane >> 3) & 1) * 16;

    // prologue: stages 0 and 1 into bufs 0, 1
    #pragma unroll
    for (int i = 0; i < 4; i++) {
        CP_ASYNC16(sA + i * 16, Ag + i * 8);
        CP_ASYNC16(sB + i * 16, Wg + i * 8);
    }
    CP_COMMIT();
    #pragma unroll
    for (int i = 0; i < 4; i++) {
        CP_ASYNC16(sA + STAGE_BYTES + i * 16, Ag + 64 + i * 8);
        CP_ASYNC16(sB + STAGE_BYTES + i * 16, Wg + 64 + i * 8);
    }
    CP_COMMIT();

    const int NSTAGE = KDIM / 32;   // 32
    int buf = 0;                    // buf of stage s (s % 3)
    for (int s = 0; s < NSTAGE; s++) {
        // wait for stage s's data (pending groups: s and possibly s+1)
        if (s + 1 < NSTAGE) { CP_WAIT1(); } else { CP_WAIT0(); }
        __syncthreads();   // data visible; all warps past iter s-1 reads

        // issue stage s+2 into buf (s+2)%3 (last read in iter s-1 -> safe)
        if (s + 2 < NSTAGE) {
            int nbuf = buf + 2; if (nbuf >= 3) nbuf -= 3;
            const uint32_t st = (uint32_t)nbuf * STAGE_BYTES;
            const size_t so = (size_t)(s + 2) * 64;
            #pragma unroll
            for (int i = 0; i < 4; i++) {
                CP_ASYNC16(sA + st + i * 16, Ag + so + i * 8);
                CP_ASYNC16(sB + st + i * 16, Wg + so + i * 8);
            }
            CP_COMMIT();
        }

        const uint32_t Abase = sb + (uint32_t)buf * STAGE_BYTES;
        const uint32_t Bbase = Abase + 128 * GR;

        #pragma unroll
        for (int kk = 0; kk < 2; kk++) {
            uint32_t aH[4][4], aL[4][4], bH[8];
            const uint32_t gH = kk * 2, gL = kk * 2 + 1;
            #pragma unroll
            for (int mt = 0; mt < 4; mt++) {
                uint32_t ad = Abase + (arow + mt * 16) * GR + aoff;
                LDM_X4(aH[mt][0], aH[mt][1], aH[mt][2], aH[mt][3], ad + gH * 32);
                LDM_X4(aL[mt][0], aL[mt][1], aL[mt][2], aL[mt][3], ad + gL * 32);
            }
            #pragma unroll
            for (int nt2 = 0; nt2 < 2; nt2++) {
                uint32_t bd = Bbase + (brow + nt2 * 16) * GR + boff;
                LDM_X4(bH[nt2*4+0], bH[nt2*4+1], bH[nt2*4+2], bH[nt2*4+3], bd + gH * 32);
            }
            #pragma unroll
            for (int mt = 0; mt < 4; mt++)
                #pragma unroll
                for (int nt = 0; nt < 4; nt++) {
                    MMA16816(c[mt][nt], aH[mt], bH[nt*2], bH[nt*2+1]);
                    MMA16816(c[mt][nt], aL[mt], bH[nt*2], bH[nt*2+1]);
                }
        }
        buf = (buf + 1 == 3) ? 0 : buf + 1;
    }

    const int mrow0 = row0 + wm * 64;
    const int ncol0 = col0 + wn * 32;
    #pragma unroll
    for (int mt = 0; mt < 4; mt++) {
        #pragma unroll
        for (int nt = 0; nt < 4; nt++) {
            const int n = ncol0 + nt * 8 + (lane & 3) * 2;
            const float2 bv = *reinterpret_cast<const float2*>(bias + n);
            const int m1 = mrow0 + mt * 16 + (lane >> 2);
            const int m2 = m1 + 8;
            float2 v1 = make_float2((c[mt][nt][0] + bv.x) * oscale,
                                    (c[mt][nt][1] + bv.y) * oscale);
            float2 v2 = make_float2((c[mt][nt][2] + bv.x) * oscale,
                                    (c[mt][nt][3] + bv.y) * oscale);
            if (mode == 1) {
                float* C = (float*)Cv;
                *reinterpret_cast<float2*>(C + (size_t)m1 * MODEL + n) = v1;
                *reinterpret_cast<float2*>(C + (size_t)m2 * MODEL + n) = v2;
            } else {
                __half* H = (__half*)Cv;
                const int hh = n >> 6, d = n & (HD - 1);
                #pragma unroll
                for (int t = 0; t < 2; t++) {
                    const int m = t ? m2 : m1;
                    const float2 v = t ? v2 : v1;
                    const int b = m >> 11, s = m & (S_LEN - 1);
                    const size_t bh = (size_t)(b * NH + hh);
                    uint32_t hi, lo;
                    if (mode == 0) {
                        size_t base = (bh * S_LEN + s) * 128 + d;
                        split2(v.x, v.y, hi, lo);
                        *reinterpret_cast<uint32_t*>(H + base)      = hi;
                        *reinterpret_cast<uint32_t*>(H + base + 64) = lo;
                    } else {  // mode 2: V transposed
                        __half hx = __float2half_rn(v.x);
                        __half hy = __float2half_rn(v.y);
                        __half lx = __float2half_rn(v.x - __half2float(hx));
                        __half ly = __float2half_rn(v.y - __half2float(hy));
                        size_t vb = bh * 128;
                        H[(vb + d)      * S_LEN + s] = hx;
                        H[(vb + d + 1)  * S_LEN + s] = hy;
                        H[(vb + 64 + d) * S_LEN + s] = lx;
                        H[(vb + 65 + d) * S_LEN + s] = ly;
                    }
                }
            }
        }
    }
}

// ======================= HMMA flash attention ==============================
// R14 winner: __launch_bounds__(256, 2), Q frags reloaded per-kt, inline
// prefetch addressing.  DOUBLE-BUFFERED K/V; all-finite softmax; 2-PASS QK
// and PV; diagonal half-tile skip.
#define SQ_OFF  0
#define SK0_OFF 34816
#define SK1_OFF 52224
#define SV0_OFF 69632
#define SV1_OFF 88064
#define ATTN_SMEM 106496
#define L2E 1.442695040888963f
#define MNEG (-60000.0f)

__global__ __launch_bounds__(256, 2) void attn_h_kernel(
    const __half* __restrict__ Qp, const __half* __restrict__ Kp,
    const __half* __restrict__ Vp, __half* __restrict__ AOp)
{
    extern __shared__ char smc[];
    const uint32_t sb = smem_u32(smc);
    const int tid  = threadIdx.x;
    const int lane = tid & 31;
    const int w    = tid >> 5;
    const int bh   = blockIdx.y;
    const int h    = bh & (NH - 1);
    const bool fwd = (h < 8);
    const int qb   = fwd ? (NQB - 1 - blockIdx.x) : blockIdx.x;
    const int q0   = qb * 128;
    const int sidx = fwd ? h : (h - 8);
    const float slope = exp2f(-(float)(sidx + 1) * 0.57312031259014454f);

    const __half* Qg = Qp + ((size_t)bh * S_LEN + q0) * 128;
    const __half* Kg = Kp + (size_t)bh * S_LEN * 128;
    const __half* Vg = Vp + (size_t)bh * 128 * S_LEN;

    const int kt_begin = fwd ? 0 : 2 * qb;
    const int kt_end   = fwd ? (2 * qb + 1) : (NKT - 1);
    const int ntiles   = kt_end - kt_begin + 1;

    // prologue: Q tile + first K/V tile (one group); addressing inline
    #pragma unroll
    for (int i = 0; i < 8; i++) {
        int id = tid + i * 256;
        CP_ASYNC16(sb + SQ_OFF + (id >> 4) * 272 + (id & 15) * 16,
                   Qg + (size_t)(id >> 4) * 128 + (id & 15) * 8);
    }
    {
        const int k0 = kt_begin * 64;
        #pragma unroll
        for (int i = 0; i < 4; i++) {
            int id = tid + i * 256;
            CP_ASYNC16(sb + SK0_OFF + (id >> 4) * 272 + (id & 15) * 16,
                       Kg + (size_t)(k0 + (id >> 4)) * 128 + (id & 15) * 8);
            CP_ASYNC16(sb + SV0_OFF + (id >> 3) * 144 + (id & 7) * 16,
                       Vg + (size_t)(id >> 3) * S_LEN + k0 + (id & 7) * 8);
        }
    }
    CP_COMMIT();
    CP_WAIT0();
    __syncthreads();

    float o[8][4];
    #pragma unroll
    for (int nt = 0; nt < 8; nt++)
        #pragma unroll
        for (int q = 0; q < 4; q++)
            o[nt][q] = 0.0f;

    const int g  = lane >> 2;
    const int tq = lane & 3;
    const int row0g = q0 + w * 16 + g;
    float m0 = MNEG, m1 = MNEG, l0 = 0.0f, l1 = 0.0f;

    const int  arow = w * 16 + (lane & 7) + ((lane >> 3) & 1) * 8;
    const uint32_t aoff = ((lane >> 4) & 1) * 16;
    const int brow_base = (lane & 7) + ((lane >> 4) & 1) * 8;
    const uint32_t boff = ((lane >> 3) & 1) * 16;

    const int dir  = fwd ? 1 : -1;
    const int dir8 = dir * 8;
    int dbase = dir * (kt_begin * 64 + tq * 2 - row0g);

    for (int it = 0; it < ntiles; it++) {
        const int sel = it & 1;
        if (it + 1 < ntiles) {
            const int nk0 = (kt_begin + it + 1) * 64;
            const uint32_t dk = sb + (((it + 1) & 1) ? SK1_OFF : SK0_OFF);
            const uint32_t dv = sb + (((it + 1) & 1) ? SV1_OFF : SV0_OFF);
            #pragma unroll
            for (int i = 0; i < 4; i++) {
                int id = tid + i * 256;
                CP_ASYNC16(dk + (id >> 4) * 272 + (id & 15) * 16,
                           Kg + (size_t)(nk0 + (id >> 4)) * 128 + (id & 15) * 8);
                CP_ASYNC16(dv + (id >> 3) * 144 + (id & 7) * 16,
                           Vg + (size_t)(id >> 3) * S_LEN + nk0 + (id & 7) * 8);
            }
            CP_COMMIT();
            CP_WAIT1();
        } else {
            CP_WAIT0();
        }
        __syncthreads();

        const bool skip = fwd ? (it == ntiles - 1 && w < 4)
                              : (it == 0 && w >= 4);
        if (!skip) {
            const uint32_t KB = sb + (sel ? SK1_OFF : SK0_OFF);
            const uint32_t VB = sb + (sel ? SV1_OFF : SV0_OFF);

            // ---- S = Q K^T (2-pass; Q frags reloaded per-kt from smem) ----
            float sc[8][4];
            #pragma unroll
            for (int nt = 0; nt < 8; nt++)
                #pragma unroll
                for (int q = 0; q < 4; q++)
                    sc[nt][q] = 0.0f;

            #pragma unroll
            for (int kt = 0; kt < 4; kt++) {
                uint32_t qh[4], ql[4];
                uint32_t qad = sb + SQ_OFF + arow * 272 + kt * 32 + aoff;
                LDM_X4(qh[0], qh[1], qh[2], qh[3], qad);
                LDM_X4(ql[0], ql[1], ql[2], ql[3], qad + 128);
                #pragma unroll
                for (int nt2 = 0; nt2 < 4; nt2++) {
                    uint32_t bd = KB + (nt2 * 16 + brow_base) * 272 + kt * 32 + boff;
                    uint32_t b0, b1, b2, b3;
                    LDM_X4(b0, b1, b2, b3, bd);
                    MMA16816(sc[2*nt2],   qh, b0, b1);
                    MMA16816(sc[2*nt2],   ql, b0, b1);
                    MMA16816(sc[2*nt2+1], qh, b2, b3);
                    MMA16816(sc[2*nt2+1], ql, b2, b3);
                }
            }

            // ---- ALiBi bias + online softmax (registers, all-finite) ----
            float mx0 = MNEG, mx1 = MNEG;
            int dn = dbase;
            #pragma unroll
            for (int nt = 0; nt < 8; nt++) {
                #pragma unroll
                for (int e = 0; e < 2; e++) {
                    const int d0 = dn + (e ? dir : 0);
                    const int d1 = d0 - dir8;
                    const float b0f = (d0 > 0) ? MNEG : slope * (float)d0;
                    const float b1f = (d1 > 0) ? MNEG : slope * (float)d1;
                    sc[nt][e]     += b0f;
                    sc[nt][2 + e] += b1f;
                    mx0 = fmaxf(mx0, sc[nt][e]);
                    mx1 = fmaxf(mx1, sc[nt][2 + e]);
                }
                dn += dir8;
            }
            mx0 = fmaxf(mx0, __shfl_xor_sync(0xffffffffu, mx0, 1));
            mx0 = fmaxf(mx0, __shfl_xor_sync(0xffffffffu, mx0, 2));
            mx1 = fmaxf(mx1, __shfl_xor_sync(0xffffffffu, mx1, 1));
            mx1 = fmaxf(mx1, __shfl_xor_sync(0xffffffffu, mx1, 2));
            const float mn0 = fmaxf(m0, mx0);
            const float mn1 = fmaxf(m1, mx1);
            const float corr0 = exp2f((m0 - mn0) * L2E);
            const float corr1 = exp2f((m1 - mn1) * L2E);
            const float s0 = mn0 * L2E, s1 = mn1 * L2E;
            float ls0 = 0.0f, ls1 = 0.0f;
            #pragma unroll
            for (int nt = 0; nt < 8; nt++) {
                float p0 = exp2f(fmaf(sc[nt][0], L2E, -s0));
                float p1 = exp2f(fmaf(sc[nt][1], L2E, -s0));
                float p2 = exp2f(fmaf(sc[nt][2], L2E, -s1));
                float p3 = exp2f(fmaf(sc[nt][3], L2E, -s1));
                sc[nt][0] = p0; sc[nt][1] = p1; sc[nt][2] = p2; sc[nt][3] = p3;
                ls0 += p0 + p1;
                ls1 += p2 + p3;
            }
            ls0 += __shfl_xor_sync(0xffffffffu, ls0, 1);
            ls0 += __shfl_xor_sync(0xffffffffu, ls0, 2);
            ls1 += __shfl_xor_sync(0xffffffffu, ls1, 1);
            ls1 += __shfl_xor_sync(0xffffffffu, ls1, 2);
            l0 = l0 * corr0 + ls0;
            l1 = l1 * corr1 + ls1;
            m0 = mn0;
            m1 = mn1;
            #pragma unroll
            for (int nt = 0; nt < 8; nt++) {
                o[nt][0] *= corr0; o[nt][1] *= corr0;
                o[nt][2] *= corr1; o[nt][3] *= corr1;
            }

            // ---- O += P V (2-pass: (Ph+Pl) x Vh) ----
            #pragma unroll
            for (int kt = 0; kt < 4; kt++) {
                uint32_t ah[4], al[4];
                split2(sc[2*kt][0],   sc[2*kt][1],   ah[0], al[0]);
                split2(sc[2*kt][2],   sc[2*kt][3],   ah[1], al[1]);
                split2(sc[2*kt+1][0], sc[2*kt+1][1], ah[2], al[2]);
                split2(sc[2*kt+1][2], sc[2*kt+1][3], ah[3], al[3]);
                #pragma unroll
                for (int nt2 = 0; nt2 < 4; nt2++) {
                    uint32_t vd = VB + (nt2 * 16 + brow_base) * 144 + kt * 32 + boff;
                    uint32_t b0, b1, b2, b3;
                    LDM_X4(b0, b1, b2, b3, vd);
                    MMA16816(o[2*nt2],   ah, b0, b1);
                    MMA16816(o[2*nt2],   al, b0, b1);
                    MMA16816(o[2*nt2+1], ah, b2, b3);
                    MMA16816(o[2*nt2+1], al, b2, b3);
                }
            }
        }
        dbase += dir * 64;
        __syncthreads();
    }

    // ---- epilogue: O /= l, write packed hi/lo into AOp (PK layout) ----
    const float inv0 = 1.0f / l0;
    const float inv1 = 1.0f / l1;
    const int bi = bh >> 4;
    const size_t ar0 = (size_t)(bi * S_LEN) + row0g;
    #pragma unroll
    for (int nt = 0; nt < 8; nt++) {
        const int cc = h * HD + nt * 8 + tq * 2;
        const size_t coff = (size_t)(cc >> 4) * 32 + (cc & 15);
        uint32_t hi, lo;
        split2(o[nt][0] * inv0, o[nt][1] * inv0, hi, lo);
        *reinterpret_cast<uint32_t*>(AOp + ar0 * PK + coff)      = hi;
        *reinterpret_cast<uint32_t*>(AOp + ar0 * PK + coff + 16) = lo;
        split2(o[nt][2] * inv1, o[nt][3] * inv1, hi, lo);
        *reinterpret_cast<uint32_t*>(AOp + (ar0 + 8) * PK + coff)      = hi;
        *reinterpret_cast<uint32_t*>(AOp + (ar0 + 8) * PK + coff + 16) = lo;
    }
}

// ---------------------------------------------------------------------------
extern "C" void kernel_launch(void* const* d_in, const int* in_sizes, int n_in,
                              void* d_out, int out_size)
{
    const float* query = (const float*)d_in[0];
    const float* key_i = (const float*)d_in[1];
    const float* value = (const float*)d_in[2];
    const float* Wq = (const float*)d_in[3];
    const float* bq = (const float*)d_in[4];
    const float* Wk = (const float*)d_in[5];
    const float* bk = (const float*)d_in[6];
    const float* Wv = (const float*)d_in[7];
    const float* bv = (const float*)d_in[8];
    const float* Wo = (const float*)d_in[9];
    const float* bo = (const float*)d_in[10];
    float* out = (float*)d_out;

    __half* hb = nullptr;
    cudaGetSymbolAddress((void**)&hb, g_h16);
    __half* AQ  = hb + HP_AQ;
    __half* AK  = hb + HP_AK;
    __half* AV  = hb + HP_AV;
    __half* AOp = hb + HP_AOP;
    __half* Wqp = hb + HP_W0;
    __half* Wkp = Wqp + HP_WSZ;
    __half* Wvp = Wkp + HP_WSZ;
    __half* Wop = Wvp + HP_WSZ;
    __half* QH  = hb + HP_QH;
    __half* KH  = hb + HP_KH;
    __half* VH  = hb + HP_VH;

    cudaFuncSetAttribute(hgemm_split_kernel,
                         cudaFuncAttributeMaxDynamicSharedMemorySize, GEMM_SMEM);
    cudaFuncSetAttribute(attn_h_kernel,
                         cudaFuncAttributeMaxDynamicSharedMemorySize, ATTN_SMEM);

    const int n4_in = M_ROWS * (KDIM / 4);
    const int n4_w  = MODEL * (KDIM / 4);

    // merged cvt: inputs (3 jobs), weights (4 jobs)
    {
        CvtPair pi0{query, AQ}, pi1{key_i, AK}, pi2{value, AV};
        cvt_multi_kernel<<<dim3(n4_in / 256, 3), 256>>>(pi0, pi1, pi2, pi0, n4_in);
        CvtPair pw0{Wq, Wqp}, pw1{Wk, Wkp}, pw2{Wv, Wvp}, pw3{Wo, Wop};
        cvt_multi_kernel<<<dim3(n4_w / 256, 4), 256>>>(pw0, pw1, pw2, pw3, n4_w);
    }

    // merged Q/K/V projection GEMMs (one launch, z selects job)
    GJob jq{AQ, Wqp, bq, QH, 0, 0.125f};
    GJob jk{AK, Wkp, bk, KH, 0, 1.0f};
    GJob jv{AV, Wvp, bv, VH, 2, 1.0f};
    hgemm_split_kernel<<<dim3(MODEL / 128, M_ROWS / 128, 3), 256, GEMM_SMEM>>>(jq, jk, jv);

    dim3 ga(NQB, B_SZ * NH);                 // (16, 64)
    attn_h_kernel<<<ga, 256, ATTN_SMEM>>>(QH, KH, VH, AOp);

    GJob jo{AOp, Wop, bo, out, 1, 1.0f};
    hgemm_split_kernel<<<dim3(MODEL / 128, M_ROWS / 128, 1), 256, GEMM_SMEM>>>(jo, jo, jo);
}

// round 16
// speedup vs baseline: 1.0501x; 1.0003x over previous
#include <cuda_runtime.h>
#include <cuda_fp16.h>
#include <cstdint>

#define B_SZ   4
#define S_LEN  2048
#define NH     16
#define HD     64
#define MODEL  1024
#define KDIM   1024
#define M_ROWS 8192
#define PK     2048      // packed halves per row (hi16|lo16 interleave per 16 elems)
#define NQB    16
#define NKT    32

// ---- packed fp16 scratch layout (halves) ----
#define HP_AQ  0ull
#define HP_AK  (1ull * M_ROWS * PK)
#define HP_AV  (2ull * M_ROWS * PK)
#define HP_AOP (3ull * M_ROWS * PK)
#define HP_WSZ ((unsigned long long)MODEL * PK)
#define HP_W0  (4ull * M_ROWS * PK)
#define BH_SZ  (64ull * S_LEN * 128)
#define HP_QH  (HP_W0 + 4ull * HP_WSZ)
#define HP_KH  (HP_QH + BH_SZ)
#define HP_VH  (HP_KH + BH_SZ)
__device__ __half g_h16[HP_VH + BH_SZ];

// ============================ helpers ======================================
__device__ __forceinline__ uint32_t smem_u32(const void* p) {
    uint32_t a;
    asm("{ .reg .u64 t; cvta.to.shared.u64 t, %1; cvt.u32.u64 %0, t; }"
        : "=r"(a) : "l"(p));
    return a;
}

// split pair of floats into packed hi half2 + lo half2
__device__ __forceinline__ void split2(float x, float y, uint32_t& hi, uint32_t& lo) {
    __half2 h = __floats2half2_rn(x, y);
    float2 f = __half22float2(h);
    __half2 l = __floats2half2_rn(x - f.x, y - f.y);
    hi = *reinterpret_cast<uint32_t*>(&h);
    lo = *reinterpret_cast<uint32_t*>(&l);
}

#define CP_ASYNC16(dst, src) \
    asm volatile("cp.async.cg.shared.global [%0], [%1], 16;" :: "r"(dst), "l"(src))
#define CP_COMMIT() asm volatile("cp.async.commit_group;")
#define CP_WAIT1()  asm volatile("cp.async.wait_group 1;")
#define CP_WAIT0()  asm volatile("cp.async.wait_group 0;")

#define LDM_X4(r0, r1, r2, r3, addr) \
    asm volatile("ldmatrix.sync.aligned.m8n8.x4.shared.b16 {%0,%1,%2,%3}, [%4];" \
                 : "=r"(r0), "=r"(r1), "=r"(r2), "=r"(r3) : "r"(addr))

#define MMA16816(c, a, b0, b1) \
    asm volatile("mma.sync.aligned.m16n8k16.row.col.f32.f16.f16.f32 " \
                 "{%0,%1,%2,%3}, {%4,%5,%6,%7}, {%8,%9}, {%0,%1,%2,%3};" \
                 : "+f"((c)[0]), "+f"((c)[1]), "+f"((c)[2]), "+f"((c)[3]) \
                 : "r"((a)[0]), "r"((a)[1]), "r"((a)[2]), "r"((a)[3]), \
                   "r"(b0), "r"(b1))

// ============================ split-convert prepass ========================
struct CvtPair { const float* s; __half* d; };

__global__ __launch_bounds__(256) void cvt_multi_kernel(
    CvtPair p0, CvtPair p1, CvtPair p2, CvtPair p3, int n4)
{
    CvtPair p = (blockIdx.y == 0) ? p0 : (blockIdx.y == 1) ? p1
              : (blockIdx.y == 2) ? p2 : p3;
    int i = blockIdx.x * blockDim.x + threadIdx.x;
    if (i >= n4) return;
    float4 v = reinterpret_cast<const float4*>(p.s)[i];
    int row  = i >> 8;
    int kpos = (i & 255) << 2;
    size_t base = (size_t)row * PK + (size_t)(kpos >> 4) * 32 + (kpos & 15);
    uint32_t h0, l0, h1, l1;
    split2(v.x, v.y, h0, l0);
    split2(v.z, v.w, h1, l1);
    *reinterpret_cast<uint2*>(p.d + base)      = make_uint2(h0, h1);
    *reinterpret_cast<uint2*>(p.d + base + 16) = make_uint2(l0, l1);
}

// ============================ fp16-split HMMA GEMM =========================
// C = A @ W^T + bias.  CTA tile 128x128, 8 warps (64x32 warp tile).
// 3-STAGE cp.async ring, ONE __syncthreads per K-stage; 2-PASS (Ah+Al) x Wh.
// R16: all 16 hi-MMAs issued before all 16 lo-MMAs per kk -> accumulator RAW
// distance 16 (was 1).  Per-accumulator order hi->lo preserved (bit-identical).
// __launch_bounds__(256, 2): 2 CTAs/SM.
struct GJob {
    const __half* A;
    const __half* W;
    const float*  bias;
    void*         C;
    int           mode;
    float         oscale;
};

#define GR 144
#define STAGE_BYTES (2 * 128 * GR)  // A tile + B tile = 36864
#define GEMM_SMEM (3 * STAGE_BYTES) // 110592

__global__ __launch_bounds__(256, 2) void hgemm_split_kernel(GJob j0, GJob j1, GJob j2)
{
    const GJob J = (blockIdx.z == 0) ? j0 : (blockIdx.z == 1) ? j1 : j2;
    const __half* Ap = J.A;
    const __half* Wp = J.W;
    const float* bias = J.bias;
    void* Cv = J.C;
    const int mode = J.mode;
    const float oscale = J.oscale;

    extern __shared__ char smem[];
    const uint32_t sb = smem_u32(smem);
    const int tid  = threadIdx.x;
    const int lane = tid & 31;
    const int wid  = tid >> 5;
    const int wm   = wid & 1;        // 2 warp-rows x 64
    const int wn   = wid >> 1;       // 4 warp-cols x 32

    const int row0 = blockIdx.y * 128;
    const int col0 = blockIdx.x * 128;

    const int lrow = tid >> 1;
    const int lhalf = (tid & 1) * 4;
    const __half* Ag = Ap + (size_t)(row0 + lrow) * PK + lhalf * 8;
    const __half* Wg = Wp + (size_t)(col0 + lrow) * PK + lhalf * 8;
    const uint32_t sA = sb + lrow * GR + lhalf * 16;
    const uint32_t sB = sA + 128 * GR;

    float c[4][4][4];
    #pragma unroll
    for (int mt = 0; mt < 4; mt++)
        #pragma unroll
        for (int nt = 0; nt < 4; nt++)
            #pragma unroll
            for (int q = 0; q < 4; q++)
                c[mt][nt][q] = 0.0f;

    const int arow = wm * 64 + (lane & 7) + ((lane >> 3) & 1) * 8;
    const uint32_t aoff = ((lane >> 4) & 1) * 16;
    const int brow = wn * 32 + (lane & 7) + ((lane >> 4) & 1) * 8;
    const uint32_t boff = ((lane >> 3) & 1) * 16;

    // prologue: stages 0 and 1 into bufs 0, 1
    #pragma unroll
    for (int i = 0; i < 4; i++) {
        CP_ASYNC16(sA + i * 16, Ag + i * 8);
        CP_ASYNC16(sB + i * 16, Wg + i * 8);
    }
    CP_COMMIT();
    #pragma unroll
    for (int i = 0; i < 4; i++) {
        CP_ASYNC16(sA + STAGE_BYTES + i * 16, Ag + 64 + i * 8);
        CP_ASYNC16(sB + STAGE_BYTES + i * 16, Wg + 64 + i * 8);
    }
    CP_COMMIT();

    const int NSTAGE = KDIM / 32;   // 32
    int buf = 0;
    for (int s = 0; s < NSTAGE; s++) {
        if (s + 1 < NSTAGE) { CP_WAIT1(); } else { CP_WAIT0(); }
        __syncthreads();

        if (s + 2 < NSTAGE) {
            int nbuf = buf + 2; if (nbuf >= 3) nbuf -= 3;
            const uint32_t st = (uint32_t)nbuf * STAGE_BYTES;
            const size_t so = (size_t)(s + 2) * 64;
            #pragma unroll
            for (int i = 0; i < 4; i++) {
                CP_ASYNC16(sA + st + i * 16, Ag + so + i * 8);
                CP_ASYNC16(sB + st + i * 16, Wg + so + i * 8);
            }
            CP_COMMIT();
        }

        const uint32_t Abase = sb + (uint32_t)buf * STAGE_BYTES;
        const uint32_t Bbase = Abase + 128 * GR;

        #pragma unroll
        for (int kk = 0; kk < 2; kk++) {
            uint32_t aH[4][4], aL[4][4], bH[8];
            const uint32_t gH = kk * 2, gL = kk * 2 + 1;
            #pragma unroll
            for (int mt = 0; mt < 4; mt++) {
                uint32_t ad = Abase + (arow + mt * 16) * GR + aoff;
                LDM_X4(aH[mt][0], aH[mt][1], aH[mt][2], aH[mt][3], ad + gH * 32);
                LDM_X4(aL[mt][0], aL[mt][1], aL[mt][2], aL[mt][3], ad + gL * 32);
            }
            #pragma unroll
            for (int nt2 = 0; nt2 < 2; nt2++) {
                uint32_t bd = Bbase + (brow + nt2 * 16) * GR + boff;
                LDM_X4(bH[nt2*4+0], bH[nt2*4+1], bH[nt2*4+2], bH[nt2*4+3], bd + gH * 32);
            }
            // R16: all hi-MMAs first (16 independent accumulators) ...
            #pragma unroll
            for (int mt = 0; mt < 4; mt++)
                #pragma unroll
                for (int nt = 0; nt < 4; nt++)
                    MMA16816(c[mt][nt], aH[mt], bH[nt*2], bH[nt*2+1]);
            // ... then all lo-MMAs (RAW distance 16 per accumulator)
            #pragma unroll
            for (int mt = 0; mt < 4; mt++)
                #pragma unroll
                for (int nt = 0; nt < 4; nt++)
                    MMA16816(c[mt][nt], aL[mt], bH[nt*2], bH[nt*2+1]);
        }
        buf = (buf + 1 == 3) ? 0 : buf + 1;
    }

    const int mrow0 = row0 + wm * 64;
    const int ncol0 = col0 + wn * 32;
    #pragma unroll
    for (int mt = 0; mt < 4; mt++) {
        #pragma unroll
        for (int nt = 0; nt < 4; nt++) {
            const int n = ncol0 + nt * 8 + (lane & 3) * 2;
            const float2 bv = *reinterpret_cast<const float2*>(bias + n);
            const int m1 = mrow0 + mt * 16 + (lane >> 2);
            const int m2 = m1 + 8;
            float2 v1 = make_float2((c[mt][nt][0] + bv.x) * oscale,
                                    (c[mt][nt][1] + bv.y) * oscale);
            float2 v2 = make_float2((c[mt][nt][2] + bv.x) * oscale,
                                    (c[mt][nt][3] + bv.y) * oscale);
            if (mode == 1) {
                float* C = (float*)Cv;
                *reinterpret_cast<float2*>(C + (size_t)m1 * MODEL + n) = v1;
                *reinterpret_cast<float2*>(C + (size_t)m2 * MODEL + n) = v2;
            } else {
                __half* H = (__half*)Cv;
                const int hh = n >> 6, d = n & (HD - 1);
                #pragma unroll
                for (int t = 0; t < 2; t++) {
                    const int m = t ? m2 : m1;
                    const float2 v = t ? v2 : v1;
                    const int b = m >> 11, s = m & (S_LEN - 1);
                    const size_t bh = (size_t)(b * NH + hh);
                    uint32_t hi, lo;
                    if (mode == 0) {
                        size_t base = (bh * S_LEN + s) * 128 + d;
                        split2(v.x, v.y, hi, lo);
                        *reinterpret_cast<uint32_t*>(H + base)      = hi;
                        *reinterpret_cast<uint32_t*>(H + base + 64) = lo;
                    } else {  // mode 2: V transposed
                        __half hx = __float2half_rn(v.x);
                        __half hy = __float2half_rn(v.y);
                        __half lx = __float2half_rn(v.x - __half2float(hx));
                        __half ly = __float2half_rn(v.y - __half2float(hy));
                        size_t vb = bh * 128;
                        H[(vb + d)      * S_LEN + s] = hx;
                        H[(vb + d + 1)  * S_LEN + s] = hy;
                        H[(vb + 64 + d) * S_LEN + s] = lx;
                        H[(vb + 65 + d) * S_LEN + s] = ly;
                    }
                }
            }
        }
    }
}

// ======================= HMMA flash attention ==============================
// R14 base + R16 MMA reorder: hi,hi,lo,lo per nt2 group (RAW distance 2).
// __launch_bounds__(256, 2); Q frags reloaded per-kt; double-buffered K/V;
// all-finite softmax; 2-PASS QK and PV; diagonal half-tile skip.
#define SQ_OFF  0
#define SK0_OFF 34816
#define SK1_OFF 52224
#define SV0_OFF 69632
#define SV1_OFF 88064
#define ATTN_SMEM 106496
#define L2E 1.442695040888963f
#define MNEG (-60000.0f)

__global__ __launch_bounds__(256, 2) void attn_h_kernel(
    const __half* __restrict__ Qp, const __half* __restrict__ Kp,
    const __half* __restrict__ Vp, __half* __restrict__ AOp)
{
    extern __shared__ char smc[];
    const uint32_t sb = smem_u32(smc);
    const int tid  = threadIdx.x;
    const int lane = tid & 31;
    const int w    = tid >> 5;
    const int bh   = blockIdx.y;
    const int h    = bh & (NH - 1);
    const bool fwd = (h < 8);
    const int qb   = fwd ? (NQB - 1 - blockIdx.x) : blockIdx.x;
    const int q0   = qb * 128;
    const int sidx = fwd ? h : (h - 8);
    const float slope = exp2f(-(float)(sidx + 1) * 0.57312031259014454f);

    const __half* Qg = Qp + ((size_t)bh * S_LEN + q0) * 128;
    const __half* Kg = Kp + (size_t)bh * S_LEN * 128;
    const __half* Vg = Vp + (size_t)bh * 128 * S_LEN;

    const int kt_begin = fwd ? 0 : 2 * qb;
    const int kt_end   = fwd ? (2 * qb + 1) : (NKT - 1);
    const int ntiles   = kt_end - kt_begin + 1;

    // prologue: Q tile + first K/V tile (one group); addressing inline
    #pragma unroll
    for (int i = 0; i < 8; i++) {
        int id = tid + i * 256;
        CP_ASYNC16(sb + SQ_OFF + (id >> 4) * 272 + (id & 15) * 16,
                   Qg + (size_t)(id >> 4) * 128 + (id & 15) * 8);
    }
    {
        const int k0 = kt_begin * 64;
        #pragma unroll
        for (int i = 0; i < 4; i++) {
            int id = tid + i * 256;
            CP_ASYNC16(sb + SK0_OFF + (id >> 4) * 272 + (id & 15) * 16,
                       Kg + (size_t)(k0 + (id >> 4)) * 128 + (id & 15) * 8);
            CP_ASYNC16(sb + SV0_OFF + (id >> 3) * 144 + (id & 7) * 16,
                       Vg + (size_t)(id >> 3) * S_LEN + k0 + (id & 7) * 8);
        }
    }
    CP_COMMIT();
    CP_WAIT0();
    __syncthreads();

    float o[8][4];
    #pragma unroll
    for (int nt = 0; nt < 8; nt++)
        #pragma unroll
        for (int q = 0; q < 4; q++)
            o[nt][q] = 0.0f;

    const int g  = lane >> 2;
    const int tq = lane & 3;
    const int row0g = q0 + w * 16 + g;
    float m0 = MNEG, m1 = MNEG, l0 = 0.0f, l1 = 0.0f;

    const int  arow = w * 16 + (lane & 7) + ((lane >> 3) & 1) * 8;
    const uint32_t aoff = ((lane >> 4) & 1) * 16;
    const int brow_base = (lane & 7) + ((lane >> 4) & 1) * 8;
    const uint32_t boff = ((lane >> 3) & 1) * 16;

    const int dir  = fwd ? 1 : -1;
    const int dir8 = dir * 8;
    int dbase = dir * (kt_begin * 64 + tq * 2 - row0g);

    for (int it = 0; it < ntiles; it++) {
        const int sel = it & 1;
        if (it + 1 < ntiles) {
            const int nk0 = (kt_begin + it + 1) * 64;
            const uint32_t dk = sb + (((it + 1) & 1) ? SK1_OFF : SK0_OFF);
            const uint32_t dv = sb + (((it + 1) & 1) ? SV1_OFF : SV0_OFF);
            #pragma unroll
            for (int i = 0; i < 4; i++) {
                int id = tid + i * 256;
                CP_ASYNC16(dk + (id >> 4) * 272 + (id & 15) * 16,
                           Kg + (size_t)(nk0 + (id >> 4)) * 128 + (id & 15) * 8);
                CP_ASYNC16(dv + (id >> 3) * 144 + (id & 7) * 16,
                           Vg + (size_t)(id >> 3) * S_LEN + nk0 + (id & 7) * 8);
            }
            CP_COMMIT();
            CP_WAIT1();
        } else {
            CP_WAIT0();
        }
        __syncthreads();

        const bool skip = fwd ? (it == ntiles - 1 && w < 4)
                              : (it == 0 && w >= 4);
        if (!skip) {
            const uint32_t KB = sb + (sel ? SK1_OFF : SK0_OFF);
            const uint32_t VB = sb + (sel ? SV1_OFF : SV0_OFF);

            // ---- S = Q K^T (2-pass; hi,hi,lo,lo per nt2 group) ----
            float sc[8][4];
            #pragma unroll
            for (int nt = 0; nt < 8; nt++)
                #pragma unroll
                for (int q = 0; q < 4; q++)
                    sc[nt][q] = 0.0f;

            #pragma unroll
            for (int kt = 0; kt < 4; kt++) {
                uint32_t qh[4], ql[4];
                uint32_t qad = sb + SQ_OFF + arow * 272 + kt * 32 + aoff;
                LDM_X4(qh[0], qh[1], qh[2], qh[3], qad);
                LDM_X4(ql[0], ql[1], ql[2], ql[3], qad + 128);
                #pragma unroll
                for (int nt2 = 0; nt2 < 4; nt2++) {
                    uint32_t bd = KB + (nt2 * 16 + brow_base) * 272 + kt * 32 + boff;
                    uint32_t b0, b1, b2, b3;
                    LDM_X4(b0, b1, b2, b3, bd);
                    MMA16816(sc[2*nt2],   qh, b0, b1);
                    MMA16816(sc[2*nt2+1], qh, b2, b3);
                    MMA16816(sc[2*nt2],   ql, b0, b1);
                    MMA16816(sc[2*nt2+1], ql, b2, b3);
                }
            }

            // ---- ALiBi bias + online softmax (registers, all-finite) ----
            float mx0 = MNEG, mx1 = MNEG;
            int dn = dbase;
            #pragma unroll
            for (int nt = 0; nt < 8; nt++) {
                #pragma unroll
                for (int e = 0; e < 2; e++) {
                    const int d0 = dn + (e ? dir : 0);
                    const int d1 = d0 - dir8;
                    const float b0f = (d0 > 0) ? MNEG : slope * (float)d0;
                    const float b1f = (d1 > 0) ? MNEG : slope * (float)d1;
                    sc[nt][e]     += b0f;
                    sc[nt][2 + e] += b1f;
                    mx0 = fmaxf(mx0, sc[nt][e]);
                    mx1 = fmaxf(mx1, sc[nt][2 + e]);
                }
                dn += dir8;
            }
            mx0 = fmaxf(mx0, __shfl_xor_sync(0xffffffffu, mx0, 1));
            mx0 = fmaxf(mx0, __shfl_xor_sync(0xffffffffu, mx0, 2));
            mx1 = fmaxf(mx1, __shfl_xor_sync(0xffffffffu, mx1, 1));
            mx1 = fmaxf(mx1, __shfl_xor_sync(0xffffffffu, mx1, 2));
            const float mn0 = fmaxf(m0, mx0);
            const float mn1 = fmaxf(m1, mx1);
            const float corr0 = exp2f((m0 - mn0) * L2E);
            const float corr1 = exp2f((m1 - mn1) * L2E);
            const float s0 = mn0 * L2E, s1 = mn1 * L2E;
            float ls0 = 0.0f, ls1 = 0.0f;
            #pragma unroll
            for (int nt = 0; nt < 8; nt++) {
                float p0 = exp2f(fmaf(sc[nt][0], L2E, -s0));
                float p1 = exp2f(fmaf(sc[nt][1], L2E, -s0));
                float p2 = exp2f(fmaf(sc[nt][2], L2E, -s1));
                float p3 = exp2f(fmaf(sc[nt][3], L2E, -s1));
                sc[nt][0] = p0; sc[nt][1] = p1; sc[nt][2] = p2; sc[nt][3] = p3;
                ls0 += p0 + p1;
                ls1 += p2 + p3;
            }
            ls0 += __shfl_xor_sync(0xffffffffu, ls0, 1);
            ls0 += __shfl_xor_sync(0xffffffffu, ls0, 2);
            ls1 += __shfl_xor_sync(0xffffffffu, ls1, 1);
            ls1 += __shfl_xor_sync(0xffffffffu, ls1, 2);
            l0 = l0 * corr0 + ls0;
            l1 = l1 * corr1 + ls1;
            m0 = mn0;
            m1 = mn1;
            #pragma unroll
            for (int nt = 0; nt < 8; nt++) {
                o[nt][0] *= corr0; o[nt][1] *= corr0;
                o[nt][2] *= corr1; o[nt][3] *= corr1;
            }

            // ---- O += P V (2-pass; hi,hi,lo,lo per nt2 group) ----
            #pragma unroll
            for (int kt = 0; kt < 4; kt++) {
                uint32_t ah[4], al[4];
                split2(sc[2*kt][0],   sc[2*kt][1],   ah[0], al[0]);
                split2(sc[2*kt][2],   sc[2*kt][3],   ah[1], al[1]);
                split2(sc[2*kt+1][0], sc[2*kt+1][1], ah[2], al[2]);
                split2(sc[2*kt+1][2], sc[2*kt+1][3], ah[3], al[3]);
                #pragma unroll
                for (int nt2 = 0; nt2 < 4; nt2++) {
                    uint32_t vd = VB + (nt2 * 16 + brow_base) * 144 + kt * 32 + boff;
                    uint32_t b0, b1, b2, b3;
                    LDM_X4(b0, b1, b2, b3, vd);
                    MMA16816(o[2*nt2],   ah, b0, b1);
                    MMA16816(o[2*nt2+1], ah, b2, b3);
                    MMA16816(o[2*nt2],   al, b0, b1);
                    MMA16816(o[2*nt2+1], al, b2, b3);
                }
            }
        }
        dbase += dir * 64;
        __syncthreads();
    }

    // ---- epilogue: O /= l, write packed hi/lo into AOp (PK layout) ----
    const float inv0 = 1.0f / l0;
    const float inv1 = 1.0f / l1;
    const int bi = bh >> 4;
    const size_t ar0 = (size_t)(bi * S_LEN) + row0g;
    #pragma unroll
    for (int nt = 0; nt < 8; nt++) {
        const int cc = h * HD + nt * 8 + tq * 2;
        const size_t coff = (size_t)(cc >> 4) * 32 + (cc & 15);
        uint32_t hi, lo;
        split2(o[nt][0] * inv0, o[nt][1] * inv0, hi, lo);
        *reinterpret_cast<uint32_t*>(AOp + ar0 * PK + coff)      = hi;
        *reinterpret_cast<uint32_t*>(AOp + ar0 * PK + coff + 16) = lo;
        split2(o[nt][2] * inv1, o[nt][3] * inv1, hi, lo);
        *reinterpret_cast<uint32_t*>(AOp + (ar0 + 8) * PK + coff)      = hi;
        *reinterpret_cast<uint32_t*>(AOp + (ar0 + 8) * PK + coff + 16) = lo;
    }
}

// ---------------------------------------------------------------------------
extern "C" void kernel_launch(void* const* d_in, const int* in_sizes, int n_in,
                              void* d_out, int out_size)
{
    const float* query = (const float*)d_in[0];
    const float* key_i = (const float*)d_in[1];
    const float* value = (const float*)d_in[2];
    const float* Wq = (const float*)d_in[3];
    const float* bq = (const float*)d_in[4];
    const float* Wk = (const float*)d_in[5];
    const float* bk = (const float*)d_in[6];
    const float* Wv = (const float*)d_in[7];
    const float* bv = (const float*)d_in[8];
    const float* Wo = (const float*)d_in[9];
    const float* bo = (const float*)d_in[10];
    float* out = (float*)d_out;

    __half* hb = nullptr;
    cudaGetSymbolAddress((void**)&hb, g_h16);
    __half* AQ  = hb + HP_AQ;
    __half* AK  = hb + HP_AK;
    __half* AV  = hb + HP_AV;
    __half* AOp = hb + HP_AOP;
    __half* Wqp = hb + HP_W0;
    __half* Wkp = Wqp + HP_WSZ;
    __half* Wvp = Wkp + HP_WSZ;
    __half* Wop = Wvp + HP_WSZ;
    __half* QH  = hb + HP_QH;
    __half* KH  = hb + HP_KH;
    __half* VH  = hb + HP_VH;

    cudaFuncSetAttribute(hgemm_split_kernel,
                         cudaFuncAttributeMaxDynamicSharedMemorySize, GEMM_SMEM);
    cudaFuncSetAttribute(attn_h_kernel,
                         cudaFuncAttributeMaxDynamicSharedMemorySize, ATTN_SMEM);

    const int n4_in = M_ROWS * (KDIM / 4);
    const int n4_w  = MODEL * (KDIM / 4);

    // merged cvt: inputs (3 jobs), weights (4 jobs)
    {
        CvtPair pi0{query, AQ}, pi1{key_i, AK}, pi2{value, AV};
        cvt_multi_kernel<<<dim3(n4_in / 256, 3), 256>>>(pi0, pi1, pi2, pi0, n4_in);
        CvtPair pw0{Wq, Wqp}, pw1{Wk, Wkp}, pw2{Wv, Wvp}, pw3{Wo, Wop};
        cvt_multi_kernel<<<dim3(n4_w / 256, 4), 256>>>(pw0, pw1, pw2, pw3, n4_w);
    }

    // merged Q/K/V projection GEMMs (one launch, z selects job)
    GJob jq{AQ, Wqp, bq, QH, 0, 0.125f};
    GJob jk{AK, Wkp, bk, KH, 0, 1.0f};
    GJob jv{AV, Wvp, bv, VH, 2, 1.0f};
    hgemm_split_kernel<<<dim3(MODEL / 128, M_ROWS / 128, 3), 256, GEMM_SMEM>>>(jq, jk, jv);

    dim3 ga(NQB, B_SZ * NH);                 // (16, 64)
    attn_h_kernel<<<ga, 256, ATTN_SMEM>>>(QH, KH, VH, AOp);

    GJob jo{AOp, Wop, bo, out, 1, 1.0f};
    hgemm_split_kernel<<<dim3(MODEL / 128, M_ROWS / 128, 1), 256, GEMM_SMEM>>>(jo, jo, jo);
}

// round 17
// speedup vs baseline: 1.2196x; 1.1614x over previous
#include <cuda_runtime.h>
#include <cuda_fp16.h>
#include <cstdint>

#define B_SZ   4
#define S_LEN  2048
#define NH     16
#define HD     64
#define MODEL  1024
#define KDIM   1024
#define M_ROWS 8192
#define PK     2048      // packed halves per row (hi16|lo16 interleave per 16 elems)
#define NQB    16
#define NKT    32

// ---- packed fp16 scratch layout (halves) ----
#define HP_AQ  0ull
#define HP_AK  (1ull * M_ROWS * PK)
#define HP_AV  (2ull * M_ROWS * PK)
#define HP_AOP (3ull * M_ROWS * PK)
#define HP_WSZ ((unsigned long long)MODEL * KDIM)        // plain fp16 weights
#define HP_W0  (4ull * M_ROWS * PK)
#define BH_SZ  (64ull * S_LEN * 128)                     // Q: hi+lo
#define KV_SZ  (64ull * S_LEN * 64)                      // K/V: hi only
#define HP_QH  (HP_W0 + 4ull * HP_WSZ)
#define HP_KH  (HP_QH + BH_SZ)
#define HP_VH  (HP_KH + KV_SZ)
__device__ __half g_h16[HP_VH + KV_SZ];

// ============================ helpers ======================================
__device__ __forceinline__ uint32_t smem_u32(const void* p) {
    uint32_t a;
    asm("{ .reg .u64 t; cvta.to.shared.u64 t, %1; cvt.u32.u64 %0, t; }"
        : "=r"(a) : "l"(p));
    return a;
}

// split pair of floats into packed hi half2 + lo half2
__device__ __forceinline__ void split2(float x, float y, uint32_t& hi, uint32_t& lo) {
    __half2 h = __floats2half2_rn(x, y);
    float2 f = __half22float2(h);
    __half2 l = __floats2half2_rn(x - f.x, y - f.y);
    hi = *reinterpret_cast<uint32_t*>(&h);
    lo = *reinterpret_cast<uint32_t*>(&l);
}

#define CP_ASYNC16(dst, src) \
    asm volatile("cp.async.cg.shared.global [%0], [%1], 16;" :: "r"(dst), "l"(src))
#define CP_COMMIT() asm volatile("cp.async.commit_group;")
#define CP_WAIT1()  asm volatile("cp.async.wait_group 1;")
#define CP_WAIT0()  asm volatile("cp.async.wait_group 0;")

#define LDM_X4(r0, r1, r2, r3, addr) \
    asm volatile("ldmatrix.sync.aligned.m8n8.x4.shared.b16 {%0,%1,%2,%3}, [%4];" \
                 : "=r"(r0), "=r"(r1), "=r"(r2), "=r"(r3) : "r"(addr))

#define MMA16816(c, a, b0, b1) \
    asm volatile("mma.sync.aligned.m16n8k16.row.col.f32.f16.f16.f32 " \
                 "{%0,%1,%2,%3}, {%4,%5,%6,%7}, {%8,%9}, {%0,%1,%2,%3};" \
                 : "+f"((c)[0]), "+f"((c)[1]), "+f"((c)[2]), "+f"((c)[3]) \
                 : "r"((a)[0]), "r"((a)[1]), "r"((a)[2]), "r"((a)[3]), \
                   "r"(b0), "r"(b1))

// ============================ split-convert prepass ========================
struct CvtPair { const float* s; __half* d; };

// inputs: PK hi/lo layout (A operand needs the 22-bit split)
__global__ __launch_bounds__(256) void cvt_multi_kernel(
    CvtPair p0, CvtPair p1, CvtPair p2, int n4)
{
    CvtPair p = (blockIdx.y == 0) ? p0 : (blockIdx.y == 1) ? p1 : p2;
    int i = blockIdx.x * blockDim.x + threadIdx.x;
    if (i >= n4) return;
    float4 v = reinterpret_cast<const float4*>(p.s)[i];
    int row  = i >> 8;
    int kpos = (i & 255) << 2;
    size_t base = (size_t)row * PK + (size_t)(kpos >> 4) * 32 + (kpos & 15);
    uint32_t h0, l0, h1, l1;
    split2(v.x, v.y, h0, l0);
    split2(v.z, v.w, h1, l1);
    *reinterpret_cast<uint2*>(p.d + base)      = make_uint2(h0, h1);
    *reinterpret_cast<uint2*>(p.d + base + 16) = make_uint2(l0, l1);
}

// weights: plain fp16 [n][1024] (B operand only uses hi)
__global__ __launch_bounds__(256) void cvt_w_kernel(
    CvtPair p0, CvtPair p1, CvtPair p2, CvtPair p3, int n4)
{
    CvtPair p = (blockIdx.y == 0) ? p0 : (blockIdx.y == 1) ? p1
              : (blockIdx.y == 2) ? p2 : p3;
    int i = blockIdx.x * blockDim.x + threadIdx.x;
    if (i >= n4) return;
    float4 v = reinterpret_cast<const float4*>(p.s)[i];
    __half2 a = __floats2half2_rn(v.x, v.y);
    __half2 b = __floats2half2_rn(v.z, v.w);
    *reinterpret_cast<uint2*>(p.d + (size_t)i * 4) =
        make_uint2(*reinterpret_cast<uint32_t*>(&a), *reinterpret_cast<uint32_t*>(&b));
}

// ============================ fp16-split HMMA GEMM =========================
// C = A @ W^T + bias.  CTA 128x128, 8 warps (64x32 warp tile).
// A in PK hi/lo layout (2-pass (Ah+Al) x Wh); W plain fp16 [n][1024] (hi-only).
// 3-stage cp.async ring, one barrier/stage; __launch_bounds__(256, 2).
// mode 0: Q packed [bh][s][hi64|lo64] (scaled); mode 1: fp32 [M,1024];
// mode 2: V hi-only transposed [bh][d 0..63][s]; mode 3: K hi-only [bh][s][64].
struct GJob {
    const __half* A;
    const __half* W;
    const float*  bias;
    void*         C;
    int           mode;
    float         oscale;
};

#define GR   144
#define GRB  80
#define A_BYTES (128 * GR)                  // 18432
#define B_BYTES (128 * GRB)                 // 10240
#define STAGE_BYTES (A_BYTES + B_BYTES)     // 28672
#define GEMM_SMEM (3 * STAGE_BYTES)         // 86016

__global__ __launch_bounds__(256, 2) void hgemm_split_kernel(GJob j0, GJob j1, GJob j2)
{
    const GJob J = (blockIdx.z == 0) ? j0 : (blockIdx.z == 1) ? j1 : j2;
    const __half* Ap = J.A;
    const __half* Wp = J.W;
    const float* bias = J.bias;
    void* Cv = J.C;
    const int mode = J.mode;
    const float oscale = J.oscale;

    extern __shared__ char smem[];
    const uint32_t sb = smem_u32(smem);
    const int tid  = threadIdx.x;
    const int lane = tid & 31;
    const int wid  = tid >> 5;
    const int wm   = wid & 1;        // 2 warp-rows x 64
    const int wn   = wid >> 1;       // 4 warp-cols x 32

    const int row0 = blockIdx.y * 128;
    const int col0 = blockIdx.x * 128;

    const int lrow = tid >> 1;
    const int lh   = tid & 1;
    const __half* Ag = Ap + (size_t)(row0 + lrow) * PK + lh * 32;      // 4 chunks
    const __half* Wg = Wp + (size_t)(col0 + lrow) * KDIM + lh * 16;    // 2 chunks
    const uint32_t sA = sb + lrow * GR + lh * 64;
    const uint32_t sB = sb + A_BYTES + lrow * GRB + lh * 32;

    float c[4][4][4];
    #pragma unroll
    for (int mt = 0; mt < 4; mt++)
        #pragma unroll
        for (int nt = 0; nt < 4; nt++)
            #pragma unroll
            for (int q = 0; q < 4; q++)
                c[mt][nt][q] = 0.0f;

    const int arow = wm * 64 + (lane & 7) + ((lane >> 3) & 1) * 8;
    const uint32_t aoff = ((lane >> 4) & 1) * 16;
    const int brow = wn * 32 + (lane & 7) + ((lane >> 4) & 1) * 8;
    const uint32_t boff = ((lane >> 3) & 1) * 16;

    // prologue: stages 0 and 1 into bufs 0, 1
    #pragma unroll
    for (int st2 = 0; st2 < 2; st2++) {
        const uint32_t bo2 = (uint32_t)st2 * STAGE_BYTES;
        const size_t soA = (size_t)st2 * 64;
        const size_t soB = (size_t)st2 * 32;
        #pragma unroll
        for (int i = 0; i < 4; i++)
            CP_ASYNC16(sA + bo2 + i * 16, Ag + soA + i * 8);
        #pragma unroll
        for (int i = 0; i < 2; i++)
            CP_ASYNC16(sB + bo2 + i * 16, Wg + soB + i * 8);
        CP_COMMIT();
    }

    const int NSTAGE = KDIM / 32;   // 32
    int buf = 0;
    for (int s = 0; s < NSTAGE; s++) {
        if (s + 1 < NSTAGE) { CP_WAIT1(); } else { CP_WAIT0(); }
        __syncthreads();

        if (s + 2 < NSTAGE) {
            int nbuf = buf + 2; if (nbuf >= 3) nbuf -= 3;
            const uint32_t st = (uint32_t)nbuf * STAGE_BYTES;
            const size_t soA = (size_t)(s + 2) * 64;
            const size_t soB = (size_t)(s + 2) * 32;
            #pragma unroll
            for (int i = 0; i < 4; i++)
                CP_ASYNC16(sA + st + i * 16, Ag + soA + i * 8);
            #pragma unroll
            for (int i = 0; i < 2; i++)
                CP_ASYNC16(sB + st + i * 16, Wg + soB + i * 8);
            CP_COMMIT();
        }

        const uint32_t Abase = sb + (uint32_t)buf * STAGE_BYTES;
        const uint32_t Bbase = Abase + A_BYTES;

        #pragma unroll
        for (int kk = 0; kk < 2; kk++) {
            uint32_t aH[4][4], aL[4][4], bH[8];
            const uint32_t gH = kk * 2, gL = kk * 2 + 1;
            #pragma unroll
            for (int mt = 0; mt < 4; mt++) {
                uint32_t ad = Abase + (arow + mt * 16) * GR + aoff;
                LDM_X4(aH[mt][0], aH[mt][1], aH[mt][2], aH[mt][3], ad + gH * 32);
                LDM_X4(aL[mt][0], aL[mt][1], aL[mt][2], aL[mt][3], ad + gL * 32);
            }
            #pragma unroll
            for (int nt2 = 0; nt2 < 2; nt2++) {
                uint32_t bd = Bbase + (brow + nt2 * 16) * GRB + kk * 32 + boff;
                LDM_X4(bH[nt2*4+0], bH[nt2*4+1], bH[nt2*4+2], bH[nt2*4+3], bd);
            }
            #pragma unroll
            for (int mt = 0; mt < 4; mt++)
                #pragma unroll
                for (int nt = 0; nt < 4; nt++)
                    MMA16816(c[mt][nt], aH[mt], bH[nt*2], bH[nt*2+1]);
            #pragma unroll
            for (int mt = 0; mt < 4; mt++)
                #pragma unroll
                for (int nt = 0; nt < 4; nt++)
                    MMA16816(c[mt][nt], aL[mt], bH[nt*2], bH[nt*2+1]);
        }
        buf = (buf + 1 == 3) ? 0 : buf + 1;
    }

    const int mrow0 = row0 + wm * 64;
    const int ncol0 = col0 + wn * 32;
    #pragma unroll
    for (int mt = 0; mt < 4; mt++) {
        #pragma unroll
        for (int nt = 0; nt < 4; nt++) {
            const int n = ncol0 + nt * 8 + (lane & 3) * 2;
            const float2 bv = *reinterpret_cast<const float2*>(bias + n);
            const int m1 = mrow0 + mt * 16 + (lane >> 2);
            const int m2 = m1 + 8;
            float2 v1 = make_float2((c[mt][nt][0] + bv.x) * oscale,
                                    (c[mt][nt][1] + bv.y) * oscale);
            float2 v2 = make_float2((c[mt][nt][2] + bv.x) * oscale,
                                    (c[mt][nt][3] + bv.y) * oscale);
            if (mode == 1) {
                float* C = (float*)Cv;
                *reinterpret_cast<float2*>(C + (size_t)m1 * MODEL + n) = v1;
                *reinterpret_cast<float2*>(C + (size_t)m2 * MODEL + n) = v2;
            } else {
                __half* H = (__half*)Cv;
                const int hh = n >> 6, d = n & (HD - 1);
                #pragma unroll
                for (int t = 0; t < 2; t++) {
                    const int m = t ? m2 : m1;
                    const float2 v = t ? v2 : v1;
                    const int b = m >> 11, s = m & (S_LEN - 1);
                    const size_t bh = (size_t)(b * NH + hh);
                    uint32_t hi, lo;
                    if (mode == 0) {          // Q: hi+lo packed
                        size_t base = (bh * S_LEN + s) * 128 + d;
                        split2(v.x, v.y, hi, lo);
                        *reinterpret_cast<uint32_t*>(H + base)      = hi;
                        *reinterpret_cast<uint32_t*>(H + base + 64) = lo;
                    } else if (mode == 3) {   // K: hi only [bh][s][64]
                        __half2 hv = __floats2half2_rn(v.x, v.y);
                        *reinterpret_cast<uint32_t*>(H + (bh * S_LEN + s) * 64 + d) =
                            *reinterpret_cast<uint32_t*>(&hv);
                    } else {                  // mode 2: V hi only transposed
                        size_t vb = bh * 64;
                        H[(vb + d)     * S_LEN + s] = __float2half_rn(v.x);
                        H[(vb + d + 1) * S_LEN + s] = __float2half_rn(v.y);
                    }
                }
            }
        }
    }
}

// ======================= HMMA flash attention ==============================
// R17: hi-only K/V tiles (half the cp.async traffic, 144B rows).
// __launch_bounds__(256, 2); Q frags reloaded per-kt; double-buffered K/V;
// all-finite softmax; 2-PASS QK and PV; diagonal half-tile skip.
#define SQ_OFF  0
#define SK0_OFF 34816
#define SK1_OFF 44032
#define SV0_OFF 53248
#define SV1_OFF 62464
#define ATTN_SMEM 71680
#define L2E 1.442695040888963f
#define MNEG (-60000.0f)

__global__ __launch_bounds__(256, 2) void attn_h_kernel(
    const __half* __restrict__ Qp, const __half* __restrict__ Kp,
    const __half* __restrict__ Vp, __half* __restrict__ AOp)
{
    extern __shared__ char smc[];
    const uint32_t sb = smem_u32(smc);
    const int tid  = threadIdx.x;
    const int lane = tid & 31;
    const int w    = tid >> 5;
    const int bh   = blockIdx.y;
    const int h    = bh & (NH - 1);
    const bool fwd = (h < 8);
    const int qb   = fwd ? (NQB - 1 - blockIdx.x) : blockIdx.x;
    const int q0   = qb * 128;
    const int sidx = fwd ? h : (h - 8);
    const float slope = exp2f(-(float)(sidx + 1) * 0.57312031259014454f);

    const __half* Qg = Qp + ((size_t)bh * S_LEN + q0) * 128;
    const __half* Kg = Kp + (size_t)bh * S_LEN * 64;
    const __half* Vg = Vp + (size_t)bh * 64 * S_LEN;

    const int kt_begin = fwd ? 0 : 2 * qb;
    const int kt_end   = fwd ? (2 * qb + 1) : (NKT - 1);
    const int ntiles   = kt_end - kt_begin + 1;

    // prologue: Q tile (hi+lo) + first K/V tiles (hi only)
    #pragma unroll
    for (int i = 0; i < 8; i++) {
        int id = tid + i * 256;
        CP_ASYNC16(sb + SQ_OFF + (id >> 4) * 272 + (id & 15) * 16,
                   Qg + (size_t)(id >> 4) * 128 + (id & 15) * 8);
    }
    {
        const int k0 = kt_begin * 64;
        #pragma unroll
        for (int i = 0; i < 2; i++) {
            int id = tid + i * 256;
            int r = id >> 3, ch = id & 7;
            CP_ASYNC16(sb + SK0_OFF + r * 144 + ch * 16,
                       Kg + (size_t)(k0 + r) * 64 + ch * 8);
            CP_ASYNC16(sb + SV0_OFF + r * 144 + ch * 16,
                       Vg + (size_t)r * S_LEN + k0 + ch * 8);
        }
    }
    CP_COMMIT();
    CP_WAIT0();
    __syncthreads();

    float o[8][4];
    #pragma unroll
    for (int nt = 0; nt < 8; nt++)
        #pragma unroll
        for (int q = 0; q < 4; q++)
            o[nt][q] = 0.0f;

    const int g  = lane >> 2;
    const int tq = lane & 3;
    const int row0g = q0 + w * 16 + g;
    float m0 = MNEG, m1 = MNEG, l0 = 0.0f, l1 = 0.0f;

    const int  arow = w * 16 + (lane & 7) + ((lane >> 3) & 1) * 8;
    const uint32_t aoff = ((lane >> 4) & 1) * 16;
    const int brow_base = (lane & 7) + ((lane >> 4) & 1) * 8;
    const uint32_t boff = ((lane >> 3) & 1) * 16;

    const int dir  = fwd ? 1 : -1;
    const int dir8 = dir * 8;
    int dbase = dir * (kt_begin * 64 + tq * 2 - row0g);

    for (int it = 0; it < ntiles; it++) {
        const int sel = it & 1;
        if (it + 1 < ntiles) {
            const int nk0 = (kt_begin + it + 1) * 64;
            const uint32_t dk = sb + (((it + 1) & 1) ? SK1_OFF : SK0_OFF);
            const uint32_t dv = sb + (((it + 1) & 1) ? SV1_OFF : SV0_OFF);
            #pragma unroll
            for (int i = 0; i < 2; i++) {
                int id = tid + i * 256;
                int r = id >> 3, ch = id & 7;
                CP_ASYNC16(dk + r * 144 + ch * 16,
                           Kg + (size_t)(nk0 + r) * 64 + ch * 8);
                CP_ASYNC16(dv + r * 144 + ch * 16,
                           Vg + (size_t)r * S_LEN + nk0 + ch * 8);
            }
            CP_COMMIT();
            CP_WAIT1();
        } else {
            CP_WAIT0();
        }
        __syncthreads();

        const bool skip = fwd ? (it == ntiles - 1 && w < 4)
                              : (it == 0 && w >= 4);
        if (!skip) {
            const uint32_t KB = sb + (sel ? SK1_OFF : SK0_OFF);
            const uint32_t VB = sb + (sel ? SV1_OFF : SV0_OFF);

            // ---- S = Q K^T (2-pass; Q frags reloaded per-kt) ----
            float sc[8][4];
            #pragma unroll
            for (int nt = 0; nt < 8; nt++)
                #pragma unroll
                for (int q = 0; q < 4; q++)
                    sc[nt][q] = 0.0f;

            #pragma unroll
            for (int kt = 0; kt < 4; kt++) {
                uint32_t qh[4], ql[4];
                uint32_t qad = sb + SQ_OFF + arow * 272 + kt * 32 + aoff;
                LDM_X4(qh[0], qh[1], qh[2], qh[3], qad);
                LDM_X4(ql[0], ql[1], ql[2], ql[3], qad + 128);
                #pragma unroll
                for (int nt2 = 0; nt2 < 4; nt2++) {
                    uint32_t bd = KB + (nt2 * 16 + brow_base) * 144 + kt * 32 + boff;
                    uint32_t b0, b1, b2, b3;
                    LDM_X4(b0, b1, b2, b3, bd);
                    MMA16816(sc[2*nt2],   qh, b0, b1);
                    MMA16816(sc[2*nt2+1], qh, b2, b3);
                    MMA16816(sc[2*nt2],   ql, b0, b1);
                    MMA16816(sc[2*nt2+1], ql, b2, b3);
                }
            }

            // ---- ALiBi bias + online softmax (registers, all-finite) ----
            float mx0 = MNEG, mx1 = MNEG;
            int dn = dbase;
            #pragma unroll
            for (int nt = 0; nt < 8; nt++) {
                #pragma unroll
                for (int e = 0; e < 2; e++) {
                    const int d0 = dn + (e ? dir : 0);
                    const int d1 = d0 - dir8;
                    const float b0f = (d0 > 0) ? MNEG : slope * (float)d0;
                    const float b1f = (d1 > 0) ? MNEG : slope * (float)d1;
                    sc[nt][e]     += b0f;
                    sc[nt][2 + e] += b1f;
                    mx0 = fmaxf(mx0, sc[nt][e]);
                    mx1 = fmaxf(mx1, sc[nt][2 + e]);
                }
                dn += dir8;
            }
            mx0 = fmaxf(mx0, __shfl_xor_sync(0xffffffffu, mx0, 1));
            mx0 = fmaxf(mx0, __shfl_xor_sync(0xffffffffu, mx0, 2));
            mx1 = fmaxf(mx1, __shfl_xor_sync(0xffffffffu, mx1, 1));
            mx1 = fmaxf(mx1, __shfl_xor_sync(0xffffffffu, mx1, 2));
            const float mn0 = fmaxf(m0, mx0);
            const float mn1 = fmaxf(m1, mx1);
            const float corr0 = exp2f((m0 - mn0) * L2E);
            const float corr1 = exp2f((m1 - mn1) * L2E);
            const float s0 = mn0 * L2E, s1 = mn1 * L2E;
            float ls0 = 0.0f, ls1 = 0.0f;
            #pragma unroll
            for (int nt = 0; nt < 8; nt++) {
                float p0 = exp2f(fmaf(sc[nt][0], L2E, -s0));
                float p1 = exp2f(fmaf(sc[nt][1], L2E, -s0));
                float p2 = exp2f(fmaf(sc[nt][2], L2E, -s1));
                float p3 = exp2f(fmaf(sc[nt][3], L2E, -s1));
                sc[nt][0] = p0; sc[nt][1] = p1; sc[nt][2] = p2; sc[nt][3] = p3;
                ls0 += p0 + p1;
                ls1 += p2 + p3;
            }
            ls0 += __shfl_xor_sync(0xffffffffu, ls0, 1);
            ls0 += __shfl_xor_sync(0xffffffffu, ls0, 2);
            ls1 += __shfl_xor_sync(0xffffffffu, ls1, 1);
            ls1 += __shfl_xor_sync(0xffffffffu, ls1, 2);
            l0 = l0 * corr0 + ls0;
            l1 = l1 * corr1 + ls1;
            m0 = mn0;
            m1 = mn1;
            #pragma unroll
            for (int nt = 0; nt < 8; nt++) {
                o[nt][0] *= corr0; o[nt][1] *= corr0;
                o[nt][2] *= corr1; o[nt][3] *= corr1;
            }

            // ---- O += P V (2-pass: (Ph+Pl) x Vh) ----
            #pragma unroll
            for (int kt = 0; kt < 4; kt++) {
                uint32_t ah[4], al[4];
                split2(sc[2*kt][0],   sc[2*kt][1],   ah[0], al[0]);
                split2(sc[2*kt][2],   sc[2*kt][3],   ah[1], al[1]);
                split2(sc[2*kt+1][0], sc[2*kt+1][1], ah[2], al[2]);
                split2(sc[2*kt+1][2], sc[2*kt+1][3], ah[3], al[3]);
                #pragma unroll
                for (int nt2 = 0; nt2 < 4; nt2++) {
                    uint32_t vd = VB + (nt2 * 16 + brow_base) * 144 + kt * 32 + boff;
                    uint32_t b0, b1, b2, b3;
                    LDM_X4(b0, b1, b2, b3, vd);
                    MMA16816(o[2*nt2],   ah, b0, b1);
                    MMA16816(o[2*nt2+1], ah, b2, b3);
                    MMA16816(o[2*nt2],   al, b0, b1);
                    MMA16816(o[2*nt2+1], al, b2, b3);
                }
            }
        }
        dbase += dir * 64;
        __syncthreads();
    }

    // ---- epilogue: O /= l, write packed hi/lo into AOp (PK layout) ----
    const float inv0 = 1.0f / l0;
    const float inv1 = 1.0f / l1;
    const int bi = bh >> 4;
    const size_t ar0 = (size_t)(bi * S_LEN) + row0g;
    #pragma unroll
    for (int nt = 0; nt < 8; nt++) {
        const int cc = h * HD + nt * 8 + tq * 2;
        const size_t coff = (size_t)(cc >> 4) * 32 + (cc & 15);
        uint32_t hi, lo;
        split2(o[nt][0] * inv0, o[nt][1] * inv0, hi, lo);
        *reinterpret_cast<uint32_t*>(AOp + ar0 * PK + coff)      = hi;
        *reinterpret_cast<uint32_t*>(AOp + ar0 * PK + coff + 16) = lo;
        split2(o[nt][2] * inv1, o[nt][3] * inv1, hi, lo);
        *reinterpret_cast<uint32_t*>(AOp + (ar0 + 8) * PK + coff)      = hi;
        *reinterpret_cast<uint32_t*>(AOp + (ar0 + 8) * PK + coff + 16) = lo;
    }
}

// ---------------------------------------------------------------------------
extern "C" void kernel_launch(void* const* d_in, const int* in_sizes, int n_in,
                              void* d_out, int out_size)
{
    const float* query = (const float*)d_in[0];
    const float* key_i = (const float*)d_in[1];
    const float* value = (const float*)d_in[2];
    const float* Wq = (const float*)d_in[3];
    const float* bq = (const float*)d_in[4];
    const float* Wk = (const float*)d_in[5];
    const float* bk = (const float*)d_in[6];
    const float* Wv = (const float*)d_in[7];
    const float* bv = (const float*)d_in[8];
    const float* Wo = (const float*)d_in[9];
    const float* bo = (const float*)d_in[10];
    float* out = (float*)d_out;

    __half* hb = nullptr;
    cudaGetSymbolAddress((void**)&hb, g_h16);
    __half* AQ  = hb + HP_AQ;
    __half* AK  = hb + HP_AK;
    __half* AV  = hb + HP_AV;
    __half* AOp = hb + HP_AOP;
    __half* Wqp = hb + HP_W0;
    __half* Wkp = Wqp + HP_WSZ;
    __half* Wvp = Wkp + HP_WSZ;
    __half* Wop = Wvp + HP_WSZ;
    __half* QH  = hb + HP_QH;
    __half* KH  = hb + HP_KH;
    __half* VH  = hb + HP_VH;

    cudaFuncSetAttribute(hgemm_split_kernel,
                         cudaFuncAttributeMaxDynamicSharedMemorySize, GEMM_SMEM);
    cudaFuncSetAttribute(attn_h_kernel,
                         cudaFuncAttributeMaxDynamicSharedMemorySize, ATTN_SMEM);

    const int n4_in = M_ROWS * (KDIM / 4);
    const int n4_w  = MODEL * (KDIM / 4);

    // merged cvt: inputs (3 jobs, PK), weights (4 jobs, plain fp16)
    {
        CvtPair pi0{query, AQ}, pi1{key_i, AK}, pi2{value, AV};
        cvt_multi_kernel<<<dim3(n4_in / 256, 3), 256>>>(pi0, pi1, pi2, n4_in);
        CvtPair pw0{Wq, Wqp}, pw1{Wk, Wkp}, pw2{Wv, Wvp}, pw3{Wo, Wop};
        cvt_w_kernel<<<dim3(n4_w / 256, 4), 256>>>(pw0, pw1, pw2, pw3, n4_w);
    }

    // merged Q/K/V projection GEMMs (one launch, z selects job)
    GJob jq{AQ, Wqp, bq, QH, 0, 0.125f};
    GJob jk{AK, Wkp, bk, KH, 3, 1.0f};
    GJob jv{AV, Wvp, bv, VH, 2, 1.0f};
    hgemm_split_kernel<<<dim3(MODEL / 128, M_ROWS / 128, 3), 256, GEMM_SMEM>>>(jq, jk, jv);

    dim3 ga(NQB, B_SZ * NH);                 // (16, 64)
    attn_h_kernel<<<ga, 256, ATTN_SMEM>>>(QH, KH, VH, AOp);

    GJob jo{AOp, Wop, bo, out, 1, 1.0f};
    hgemm_split_kernel<<<dim3(MODEL / 128, M_ROWS / 128, 1), 256, GEMM_SMEM>>>(jo, jo, jo);
}